// round 14
// baseline (speedup 1.0000x reference)
#include <cuda_runtime.h>
#include <cuda_bf16.h>
#include <stdint.h>
#include <math.h>

#define Bb    8
#define Hh    16
#define NSEQ  1024
#define DMOD  1024
#define DHd   64
#define MR    (Bb * NSEQ)
#define EPSF  1e-9f

typedef unsigned int u32;
typedef unsigned long long u64;
typedef __nv_bfloat16 bf16;

// ---------------- scratch (device globals; allocations forbidden) -----------
__device__ __align__(16) bf16 g_qsH[MR * DMOD], g_qsL[MR * DMOD];
__device__ __align__(16) bf16 g_ksH[MR * DMOD], g_ksL[MR * DMOD];
__device__ __align__(16) bf16 g_vsH[MR * DMOD], g_vsL[MR * DMOD];
__device__ __align__(16) bf16 g_WqH[DMOD * DMOD], g_WqL[DMOD * DMOD];
__device__ __align__(16) bf16 g_WkH[DMOD * DMOD], g_WkL[DMOD * DMOD];
__device__ __align__(16) bf16 g_WvH[DMOD * DMOD], g_WvL[DMOD * DMOD];
__device__ __align__(16) bf16 g_WoH[DMOD * DMOD], g_WoL[DMOD * DMOD];
__device__ __align__(16) bf16 g_WbTH[DMOD * DMOD], g_WbTL[DMOD * DMOD];
__device__ __align__(16) bf16 g_QH[MR * DMOD], g_QL[MR * DMOD];
__device__ __align__(16) bf16 g_KH[MR * DMOD], g_KL[MR * DMOD];
__device__ __align__(16) bf16 g_VtH[MR * DMOD], g_VtL[MR * DMOD];
__device__ __align__(16) bf16 g_XWH[MR * DMOD], g_XWL[MR * DMOD];
__device__ __align__(16) bf16 g_CATH[MR * DMOD], g_CATL[MR * DMOD];
__device__ float g_L[Bb * NSEQ * NSEQ];

// ---------------- helpers ----------------------------------------------------
__device__ __forceinline__ u32 smem_u32(const void* p) {
    u32 a;
    asm("{ .reg .u64 t; cvta.to.shared.u64 t, %1; cvt.u32.u64 %0, t; }"
        : "=r"(a) : "l"(p));
    return a;
}
__device__ __forceinline__ u32 pack2(bf16 a, bf16 b) {
    __nv_bfloat162 t; t.x = a; t.y = b;
    return *reinterpret_cast<u32*>(&t);
}
__device__ __forceinline__ void split1(float v, bf16& h, bf16& l) {
    h = __float2bfloat16(v);
    l = __float2bfloat16(v - __bfloat162float(h));
}
__device__ __forceinline__ void ldm4(u32 addr, u32& r0, u32& r1, u32& r2, u32& r3) {
    asm volatile("ldmatrix.sync.aligned.m8n8.x4.shared.b16 {%0,%1,%2,%3}, [%4];"
                 : "=r"(r0), "=r"(r1), "=r"(r2), "=r"(r3) : "r"(addr));
}
__device__ __forceinline__ void mma16816(float* c, const u32* a, u32 b0, u32 b1) {
    asm volatile(
        "mma.sync.aligned.m16n8k16.row.col.f32.bf16.bf16.f32 "
        "{%0,%1,%2,%3}, {%4,%5,%6,%7}, {%8,%9}, {%0,%1,%2,%3};"
        : "+f"(c[0]), "+f"(c[1]), "+f"(c[2]), "+f"(c[3])
        : "r"(a[0]), "r"(a[1]), "r"(a[2]), "r"(a[3]), "r"(b0), "r"(b1));
}
__device__ __forceinline__ void cpa16(u32 dst, const void* src) {
    asm volatile("cp.async.cg.shared.global [%0], [%1], 16;"
                 :: "r"(dst), "l"(src) : "memory");
}
__device__ __forceinline__ void cp_commit() {
    asm volatile("cp.async.commit_group;" ::: "memory");
}
__device__ __forceinline__ u32 swz128(u32 row, u32 ch) {
    return row * 128u + ((ch ^ (row & 7u)) << 4);
}

// ---------------------------------------------------------------------------
__global__ void split_f32(const float* __restrict__ in, bf16* __restrict__ hi,
                          bf16* __restrict__ lo, int n4)
{
    int i = blockIdx.x * blockDim.x + threadIdx.x;
    if (i >= n4) return;
    float4 v = ((const float4*)in)[i];
    bf16 h0, h1, h2, h3, l0, l1, l2, l3;
    split1(v.x, h0, l0); split1(v.y, h1, l1);
    split1(v.z, h2, l2); split1(v.w, h3, l3);
    ((uint2*)hi)[i] = make_uint2(pack2(h0, h1), pack2(h2, h3));
    ((uint2*)lo)[i] = make_uint2(pack2(l0, l1), pack2(l2, l3));
}

__global__ void transpose_split(const float* __restrict__ in,
                                bf16* __restrict__ oh, bf16* __restrict__ ol)
{
    __shared__ float t[32][33];
    const int tx = threadIdx.x;
    const int x = blockIdx.x * 32 + tx;
    for (int i = threadIdx.y; i < 32; i += 8)
        t[i][tx] = in[(size_t)(blockIdx.y * 32 + i) * DMOD + x];
    __syncthreads();
    const int ox = blockIdx.y * 32 + tx;
    for (int i = threadIdx.y; i < 32; i += 8) {
        bf16 h, l;
        split1(t[tx][i], h, l);
        oh[(size_t)(blockIdx.x * 32 + i) * DMOD + ox] = h;
        ol[(size_t)(blockIdx.x * 32 + i) * DMOD + ox] = l;
    }
}

// ---------------------------------------------------------------------------
// Split-plane bf16 GEMM, 256x128 tile, 512 thr (16 warps 4x4, warp 64x32),
// K-chunk 64, 2-stage cp.async, 192KB smem, 1 CTA/SM (16 warps/SM).
// ---------------------------------------------------------------------------
template<int EPI>
__global__ __launch_bounds__(512, 1)
void bf_gemm(const bf16* __restrict__ Ah, const bf16* __restrict__ Al,
             const bf16* __restrict__ Bh, const bf16* __restrict__ Bl,
             int K, long long sAz, long long sBz,
             float* __restrict__ out0, float* __restrict__ aux,
             const float* __restrict__ bias,
             const float* __restrict__ s0, const float* __restrict__ s1,
             bf16* __restrict__ oH, bf16* __restrict__ oL)
{
    constexpr int AHI = 0;
    constexpr int ALO = 256 * 128;          // 32KB each (256 rows x 128B)
    constexpr int BHI = 2 * 256 * 128;      // 65536
    constexpr int BLO = BHI + 128 * 128;    // +16KB
    constexpr int STAGE = BLO + 128 * 128;  // 98304

    extern __shared__ char smem[];
    const u32 sb = smem_u32(smem);

    const int tid = threadIdx.x;
    const int wid = tid >> 5, lane = tid & 31;
    const int wM = wid & 3, wN = wid >> 2;
    const int z  = blockIdx.z;
    const int m0 = blockIdx.y * 256;
    const int n0 = blockIdx.x * 128;
    const int mat = lane >> 3, lir = lane & 7;
    const int rfr = (mat & 1) * 8 + lir;
    const int kcf = mat >> 1;

    const bf16* Abh = Ah + (size_t)z * sAz + (size_t)m0 * K;
    const bf16* Abl = Al + (size_t)z * sAz + (size_t)m0 * K;
    const bf16* Bbh = Bh + (size_t)z * sBz + (size_t)n0 * K;
    const bf16* Bbl = Bl + (size_t)z * sBz + (size_t)n0 * K;

    float acc[4][4][4];
#pragma unroll
    for (int i = 0; i < 4; i++)
#pragma unroll
        for (int j = 0; j < 4; j++)
#pragma unroll
            for (int e = 0; e < 4; e++) acc[i][j][e] = 0.0f;

    const int C = K >> 6;

    auto stage = [&](int c, int s) {
        const int k0 = c << 6;
        const u32 base = sb + (u32)s * STAGE;
#pragma unroll
        for (int u = tid; u < 2048; u += 512) {
            const u32 row = (u32)(u >> 3), ch = (u32)(u & 7);
            const u32 off = swz128(row, ch);
            const size_t so = (size_t)row * K + k0 + ch * 8;
            cpa16(base + AHI + off, Abh + so);
            cpa16(base + ALO + off, Abl + so);
        }
#pragma unroll
        for (int u = tid; u < 1024; u += 512) {
            const u32 row = (u32)(u >> 3), ch = (u32)(u & 7);
            const u32 off = swz128(row, ch);
            const size_t so = (size_t)row * K + k0 + ch * 8;
            cpa16(base + BHI + off, Bbh + so);
            cpa16(base + BLO + off, Bbl + so);
        }
        cp_commit();
    };

    stage(0, 0);
    for (int c = 0; c < C; c++) {
        if (c + 1 < C) {
            stage(c + 1, (c + 1) & 1);
            asm volatile("cp.async.wait_group 1;" ::: "memory");
        } else {
            asm volatile("cp.async.wait_group 0;" ::: "memory");
        }
        __syncthreads();
        const u32 bbase = sb + (u32)(c & 1) * STAGE;

#pragma unroll
        for (int ks = 0; ks < 4; ks++) {
            const u32 kch = (u32)(ks * 2 + kcf);
            u32 ah[4][4], al[4][4], bh[2][4], bl[2][4];
#pragma unroll
            for (int mi = 0; mi < 4; mi++) {
                const u32 row = (u32)(wM * 64 + mi * 16 + rfr);
                ldm4(bbase + AHI + swz128(row, kch),
                     ah[mi][0], ah[mi][1], ah[mi][2], ah[mi][3]);
            }
#pragma unroll
            for (int j = 0; j < 2; j++) {
                const u32 row = (u32)(wN * 32 + j * 16 + rfr);
                ldm4(bbase + BHI + swz128(row, kch),
                     bh[j][0], bh[j][1], bh[j][2], bh[j][3]);
            }
#pragma unroll
            for (int mi = 0; mi < 4; mi++) {
                const u32 row = (u32)(wM * 64 + mi * 16 + rfr);
                ldm4(bbase + ALO + swz128(row, kch),
                     al[mi][0], al[mi][1], al[mi][2], al[mi][3]);
            }
#pragma unroll
            for (int j = 0; j < 2; j++) {
                const u32 row = (u32)(wN * 32 + j * 16 + rfr);
                ldm4(bbase + BLO + swz128(row, kch),
                     bl[j][0], bl[j][1], bl[j][2], bl[j][3]);
            }
#pragma unroll
            for (int mi = 0; mi < 4; mi++)
#pragma unroll
                for (int ni = 0; ni < 4; ni++)
                    mma16816(acc[mi][ni], ah[mi],
                             bh[ni >> 1][ni & 1], bh[ni >> 1][(ni & 1) + 2]);
#pragma unroll
            for (int mi = 0; mi < 4; mi++)
#pragma unroll
                for (int ni = 0; ni < 4; ni++)
                    mma16816(acc[mi][ni], al[mi],
                             bh[ni >> 1][ni & 1], bh[ni >> 1][(ni & 1) + 2]);
#pragma unroll
            for (int mi = 0; mi < 4; mi++)
#pragma unroll
                for (int ni = 0; ni < 4; ni++)
                    mma16816(acc[mi][ni], ah[mi],
                             bl[ni >> 1][ni & 1], bl[ni >> 1][(ni & 1) + 2]);
        }
        __syncthreads();
    }

    const int gid = lane >> 2, t4 = lane & 3;
#pragma unroll
    for (int mi = 0; mi < 4; mi++) {
#pragma unroll
        for (int h = 0; h < 2; h++) {
            const int m = m0 + wM * 64 + mi * 16 + gid + h * 8;
#pragma unroll
            for (int ni = 0; ni < 4; ni++) {
                const int n = n0 + wN * 32 + ni * 8 + t4 * 2;
                float v0 = acc[mi][ni][h * 2 + 0];
                float v1 = acc[mi][ni][h * 2 + 1];

                if (EPI == 0) {
                    const int b = m >> 10, tok = m & 1023;
                    const int hd = n >> 6, d = n & 63;
                    bf16 h0, l0, h1, l1;
                    split1(v0 + bias[n], h0, l0);
                    split1(v1 + bias[n + 1], h1, l1);
                    const size_t ix = (((size_t)(b * Hh + hd) * NSEQ) + tok) * DHd + d;
                    *(u32*)(oH + ix) = pack2(h0, h1);
                    *(u32*)(oL + ix) = pack2(l0, l1);
                } else if (EPI == 7) {
                    const int b = m >> 10, tok = m & 1023;
                    const int hd = n >> 6, d = n & 63;
                    bf16 h0, l0, h1, l1;
                    split1(v0 + bias[n], h0, l0);
                    split1(v1 + bias[n + 1], h1, l1);
                    const size_t zz = (size_t)(b * Hh + hd);
                    oH[(zz * DHd + d) * NSEQ + tok]     = h0;
                    oH[(zz * DHd + d + 1) * NSEQ + tok] = h1;
                    oL[(zz * DHd + d) * NSEQ + tok]     = l0;
                    oL[(zz * DHd + d + 1) * NSEQ + tok] = l1;
                } else if (EPI == 2) {
                    bf16 h0, l0, h1, l1;
                    split1(v0, h0, l0); split1(v1, h1, l1);
                    const size_t ix = (size_t)m * DMOD + n;
                    *(u32*)(oH + ix) = pack2(h0, h1);
                    *(u32*)(oL + ix) = pack2(l0, l1);
                } else if (EPI == 3) {
                    const float bb0 = s0[0], lam = s1[0];
                    float p0 = 1.0f / (1.0f + __expf(-(v0 + bb0)));
                    float p1 = 1.0f / (1.0f + __expf(-(v1 + bb0)));
                    const size_t idx = ((size_t)z * NSEQ + m) * NSEQ + n;
                    *(float2*)(out0 + idx) = make_float2(p0, p1);
                    *(float2*)(aux + idx) =
                        make_float2(lam * __logf(p0 + EPSF), lam * __logf(p1 + EPSF));
                } else if (EPI == 6) {
                    *(float2*)(out0 + (size_t)m * DMOD + n) =
                        make_float2(v0 + bias[n], v1 + bias[n + 1]);
                }
            }
        }
    }
}

// ---------------------------------------------------------------------------
// Fused attention: logits + softmax + att write + P@V (register P).
// CTA = 16 q-rows x 1024 keys, 256 thr, 70656B smem, 2 CTAs/SM.
// ---------------------------------------------------------------------------
__global__ __launch_bounds__(256, 2)
void fused_attn(const bf16* __restrict__ Qh, const bf16* __restrict__ Ql,
                const bf16* __restrict__ Kh, const bf16* __restrict__ Kl,
                const bf16* __restrict__ Vth, const bf16* __restrict__ Vtl,
                const float* __restrict__ Lbuf, float* __restrict__ att,
                bf16* __restrict__ oH, bf16* __restrict__ oL)
{
    constexpr int S_AH = 0, S_AL = 2048, S_B = 4096;
    constexpr int KSTG = 32768;
    constexpr int S_WMAX = S_B + 2 * KSTG;
    constexpr int S_WSUM = S_WMAX + 512;

    extern __shared__ char smem[];
    const u32 sb = smem_u32(smem);

    const int tid = threadIdx.x;
    const int wid = tid >> 5, lane = tid & 31;
    const int z = blockIdx.y, bz = z >> 4, hz = z & 15;
    const int m0 = blockIdx.x * 16;
    const int mat = lane >> 3, lir = lane & 7;
    const int rfr = (mat & 1) * 8 + lir;
    const int kcf = mat >> 1;
    const int gid = lane >> 2, t4 = lane & 3;

    const bf16* Abh = Qh + (size_t)z * NSEQ * DHd + (size_t)m0 * DHd;
    const bf16* Abl = Ql + (size_t)z * NSEQ * DHd + (size_t)m0 * DHd;
    const bf16* Kbh = Kh + (size_t)z * NSEQ * DHd;
    const bf16* Kbl = Kl + (size_t)z * NSEQ * DHd;
    const bf16* Vbh = Vth + (size_t)z * DHd * NSEQ;
    const bf16* Vbl = Vtl + (size_t)z * DHd * NSEQ;

    if (tid < 128) {
        const u32 row = (u32)(tid >> 3), ch = (u32)(tid & 7);
        const u32 off = swz128(row, ch);
        cpa16(sb + S_AH + off, Abh + (size_t)row * DHd + ch * 8);
        cpa16(sb + S_AL + off, Abl + (size_t)row * DHd + ch * 8);
    }

    auto stageK = [&](int j, int s) {
        const u32 base = sb + S_B + (u32)s * KSTG;
#pragma unroll
        for (int u = tid; u < 1024; u += 256) {
            const u32 row = (u32)(u >> 3), ch = (u32)(u & 7);
            const u32 off = swz128(row, ch);
            const size_t so = (size_t)(j * 128 + row) * DHd + ch * 8;
            cpa16(base + off, Kbh + so);
            cpa16(base + 16384 + off, Kbl + so);
        }
        cp_commit();
    };
    auto stageV = [&](int j, int s) {
        const u32 base = sb + S_B + (u32)s * KSTG;
#pragma unroll
        for (int u = tid; u < 2048; u += 256) {
            const int sub = u >> 10, pl = (u >> 9) & 1;
            const u32 row = (u32)((u >> 3) & 63), ch = (u32)(u & 7);
            const bf16* src = (pl ? Vbl : Vbh)
                            + (size_t)row * NSEQ + j * 128 + sub * 64 + ch * 8;
            cpa16(base + (u32)sub * 16384 + (u32)pl * 8192 + swz128(row, ch), src);
        }
        cp_commit();
    };

    float acc[8][2][4];
#pragma unroll
    for (int j = 0; j < 8; j++)
#pragma unroll
        for (int n = 0; n < 2; n++)
#pragma unroll
            for (int e = 0; e < 4; e++) acc[j][n][e] = 0.0f;

    stageK(0, 0);
#pragma unroll
    for (int j = 0; j < 8; j++) {
        if (j < 7) {
            stageK(j + 1, (j + 1) & 1);
            asm volatile("cp.async.wait_group 1;" ::: "memory");
        } else {
            asm volatile("cp.async.wait_group 0;" ::: "memory");
        }
        __syncthreads();
        const u32 bbase = sb + S_B + (u32)(j & 1) * KSTG;

#pragma unroll
        for (int ks = 0; ks < 4; ks++) {
            const u32 kch = (u32)(ks * 2 + kcf);
            u32 a_h[4], a_l[4], b_h[4], b_l[4];
            ldm4(sb + S_AH + swz128((u32)rfr, kch), a_h[0], a_h[1], a_h[2], a_h[3]);
            const u32 brow = (u32)(wid * 16 + rfr);
            ldm4(bbase + swz128(brow, kch), b_h[0], b_h[1], b_h[2], b_h[3]);
            ldm4(sb + S_AL + swz128((u32)rfr, kch), a_l[0], a_l[1], a_l[2], a_l[3]);
            ldm4(bbase + 16384 + swz128(brow, kch), b_l[0], b_l[1], b_l[2], b_l[3]);
#pragma unroll
            for (int ni = 0; ni < 2; ni++) {
                mma16816(acc[j][ni], a_h, b_h[ni], b_h[ni + 2]);
                mma16816(acc[j][ni], a_l, b_h[ni], b_h[ni + 2]);
                mma16816(acc[j][ni], a_h, b_l[ni], b_l[ni + 2]);
            }
        }
        __syncthreads();
    }

    stageV(0, 0);

    float* wmax = (float*)(smem + S_WMAX);
    float* wsum = (float*)(smem + S_WSUM);

    float mx[2] = {-3.4e38f, -3.4e38f};
#pragma unroll
    for (int j = 0; j < 8; j++)
#pragma unroll
        for (int ni = 0; ni < 2; ni++) {
            const int col = j * 128 + wid * 16 + ni * 8 + t4 * 2;
#pragma unroll
            for (int h = 0; h < 2; h++) {
                const int row = m0 + gid + h * 8;
                float2 Lv = *(const float2*)(Lbuf + ((size_t)bz * NSEQ + row) * NSEQ + col);
                float s0 = acc[j][ni][h * 2 + 0] * 0.125f + Lv.x;
                float s1 = acc[j][ni][h * 2 + 1] * 0.125f + Lv.y;
                acc[j][ni][h * 2 + 0] = s0;
                acc[j][ni][h * 2 + 1] = s1;
                mx[h] = fmaxf(mx[h], fmaxf(s0, s1));
            }
        }
#pragma unroll
    for (int h = 0; h < 2; h++) {
        mx[h] = fmaxf(mx[h], __shfl_xor_sync(0xffffffffu, mx[h], 1));
        mx[h] = fmaxf(mx[h], __shfl_xor_sync(0xffffffffu, mx[h], 2));
        if (t4 == 0) wmax[(gid + h * 8) * 8 + wid] = mx[h];
    }
    __syncthreads();
    float rmax[2];
#pragma unroll
    for (int h = 0; h < 2; h++) {
        float m = wmax[(gid + h * 8) * 8 + 0];
#pragma unroll
        for (int w = 1; w < 8; w++) m = fmaxf(m, wmax[(gid + h * 8) * 8 + w]);
        rmax[h] = m;
    }
    float sm[2] = {0.0f, 0.0f};
#pragma unroll
    for (int j = 0; j < 8; j++)
#pragma unroll
        for (int ni = 0; ni < 2; ni++)
#pragma unroll
            for (int h = 0; h < 2; h++) {
                float e0 = __expf(acc[j][ni][h * 2 + 0] - rmax[h]);
                float e1 = __expf(acc[j][ni][h * 2 + 1] - rmax[h]);
                acc[j][ni][h * 2 + 0] = e0;
                acc[j][ni][h * 2 + 1] = e1;
                sm[h] += e0 + e1;
            }
#pragma unroll
    for (int h = 0; h < 2; h++) {
        sm[h] += __shfl_xor_sync(0xffffffffu, sm[h], 1);
        sm[h] += __shfl_xor_sync(0xffffffffu, sm[h], 2);
        if (t4 == 0) wsum[(gid + h * 8) * 8 + wid] = sm[h];
    }
    __syncthreads();
    float rinv[2];
#pragma unroll
    for (int h = 0; h < 2; h++) {
        float s = 0.0f;
#pragma unroll
        for (int w = 0; w < 8; w++) s += wsum[(gid + h * 8) * 8 + w];
        rinv[h] = 1.0f / s;
    }

#pragma unroll
    for (int j = 0; j < 8; j++) {
        float c00 = acc[j][0][0] * rinv[0], c01 = acc[j][0][1] * rinv[0];
        float c02 = acc[j][0][2] * rinv[1], c03 = acc[j][0][3] * rinv[1];
        float c10 = acc[j][1][0] * rinv[0], c11 = acc[j][1][1] * rinv[0];
        float c12 = acc[j][1][2] * rinv[1], c13 = acc[j][1][3] * rinv[1];
        const int col0 = j * 128 + wid * 16 + t4 * 2;
        *(float2*)(att + ((size_t)z * NSEQ + m0 + gid) * NSEQ + col0) =
            make_float2(c00, c01);
        *(float2*)(att + ((size_t)z * NSEQ + m0 + gid + 8) * NSEQ + col0) =
            make_float2(c02, c03);
        *(float2*)(att + ((size_t)z * NSEQ + m0 + gid) * NSEQ + col0 + 8) =
            make_float2(c10, c11);
        *(float2*)(att + ((size_t)z * NSEQ + m0 + gid + 8) * NSEQ + col0 + 8) =
            make_float2(c12, c13);
        bf16 h00, l00, h01, l01, h02, l02, h03, l03;
        bf16 h10, l10, h11, l11, h12, l12, h13, l13;
        split1(c00, h00, l00); split1(c01, h01, l01);
        split1(c02, h02, l02); split1(c03, h03, l03);
        split1(c10, h10, l10); split1(c11, h11, l11);
        split1(c12, h12, l12); split1(c13, h13, l13);
        acc[j][0][0] = __uint_as_float(pack2(h00, h01));
        acc[j][0][1] = __uint_as_float(pack2(h02, h03));
        acc[j][0][2] = __uint_as_float(pack2(h10, h11));
        acc[j][0][3] = __uint_as_float(pack2(h12, h13));
        acc[j][1][0] = __uint_as_float(pack2(l00, l01));
        acc[j][1][1] = __uint_as_float(pack2(l02, l03));
        acc[j][1][2] = __uint_as_float(pack2(l10, l11));
        acc[j][1][3] = __uint_as_float(pack2(l12, l13));
    }

    const int sub = wid >> 2;
    const u32 kchb = (u32)((wid & 3) * 2);
    float Oa[4][2][4];
#pragma unroll
    for (int g = 0; g < 4; g++)
#pragma unroll
        for (int ni = 0; ni < 2; ni++)
#pragma unroll
            for (int e = 0; e < 4; e++) Oa[g][ni][e] = 0.0f;

#pragma unroll
    for (int j = 0; j < 8; j++) {
        if (j < 7) {
            stageV(j + 1, (j + 1) & 1);
            asm volatile("cp.async.wait_group 1;" ::: "memory");
        } else {
            asm volatile("cp.async.wait_group 0;" ::: "memory");
        }
        __syncthreads();
        const u32 vb = sb + S_B + (u32)(j & 1) * KSTG + (u32)sub * 16384;
        const u32* Ahi = (const u32*)&acc[j][0][0];
        const u32* Alo = (const u32*)&acc[j][1][0];
#pragma unroll
        for (int g = 0; g < 4; g++) {
            const u32 vrow = (u32)(g * 16 + rfr);
            const u32 va = swz128(vrow, kchb + (u32)kcf);
            u32 vh[4], vl[4];
            ldm4(vb + va, vh[0], vh[1], vh[2], vh[3]);
            ldm4(vb + 8192 + va, vl[0], vl[1], vl[2], vl[3]);
#pragma unroll
            for (int ni = 0; ni < 2; ni++) {
                mma16816(Oa[g][ni], Ahi, vh[ni], vh[ni + 2]);
                mma16816(Oa[g][ni], Alo, vh[ni], vh[ni + 2]);
                mma16816(Oa[g][ni], Ahi, vl[ni], vl[ni + 2]);
            }
        }
        __syncthreads();
    }

    float* opart = (float*)(smem + S_B);
#pragma unroll
    for (int g = 0; g < 4; g++)
#pragma unroll
        for (int ni = 0; ni < 2; ni++) {
            const int d = g * 16 + ni * 8 + t4 * 2;
            *(float2*)(opart + (size_t)wid * 1024 + gid * 64 + d) =
                make_float2(Oa[g][ni][0], Oa[g][ni][1]);
            *(float2*)(opart + (size_t)wid * 1024 + (gid + 8) * 64 + d) =
                make_float2(Oa[g][ni][2], Oa[g][ni][3]);
        }
    __syncthreads();
#pragma unroll
    for (int u = tid; u < 512; u += 256) {
        const int row = u >> 5, d = (u & 31) * 2;
        float2 s = *(float2*)(opart + row * 64 + d);
#pragma unroll
        for (int w = 1; w < 8; w++) {
            float2 t = *(float2*)(opart + (size_t)w * 1024 + row * 64 + d);
            s.x += t.x; s.y += t.y;
        }
        bf16 h0, l0, h1, l1;
        split1(s.x, h0, l0); split1(s.y, h1, l1);
        const size_t ix = ((size_t)(bz * NSEQ + m0 + row)) * DMOD + hz * DHd + d;
        *(u32*)(oH + ix) = pack2(h0, h1);
        *(u32*)(oL + ix) = pack2(l0, l1);
    }
}

// ---------------------------------------------------------------------------
extern "C" void kernel_launch(void* const* d_in, const int* in_sizes, int n_in,
                              void* d_out, int out_size)
{
    const float* queries = (const float*)d_in[0];
    const float* keys    = (const float*)d_in[1];
    const float* values  = (const float*)d_in[2];
    const float* Wq = (const float*)d_in[3];  const float* bq = (const float*)d_in[4];
    const float* Wk = (const float*)d_in[5];  const float* bk = (const float*)d_in[6];
    const float* Wv = (const float*)d_in[7];  const float* bv = (const float*)d_in[8];
    const float* Wo = (const float*)d_in[9];  const float* bo = (const float*)d_in[10];
    const float* Wb = (const float*)d_in[11]; const float* bb = (const float*)d_in[12];
    const float* lam = (const float*)d_in[13];

    float* out_main = (float*)d_out;
    float* att      = out_main + (size_t)Bb * NSEQ * DMOD;
    float* Pout     = att + (size_t)Bb * Hh * NSEQ * NSEQ;

#define GA(sym, var) bf16* var; cudaGetSymbolAddress((void**)&var, sym)
    GA(g_qsH, qsH); GA(g_qsL, qsL); GA(g_ksH, ksH); GA(g_ksL, ksL);
    GA(g_vsH, vsH); GA(g_vsL, vsL);
    GA(g_WqH, WqH); GA(g_WqL, WqL); GA(g_WkH, WkH); GA(g_WkL, WkL);
    GA(g_WvH, WvH); GA(g_WvL, WvL); GA(g_WoH, WoH); GA(g_WoL, WoL);
    GA(g_WbTH, WbTH); GA(g_WbTL, WbTL);
    GA(g_QH, QH); GA(g_QL, QL); GA(g_KH, KH); GA(g_KL, KL);
    GA(g_VtH, VtH); GA(g_VtL, VtL);
    GA(g_XWH, XWH); GA(g_XWL, XWL);
    GA(g_CATH, CATH); GA(g_CATL, CATL);
#undef GA
    float* gL; cudaGetSymbolAddress((void**)&gL, g_L);

    const int SMG = 196608;     // 2 x 96KB stages
    const int SM_FA = 70656;

    static bool inited = false;
    static cudaStream_t st1, st2;
    static cudaEvent_t eQS, eQ, eK, eV, eWo;
    if (!inited) {
        cudaFuncSetAttribute(bf_gemm<0>, cudaFuncAttributeMaxDynamicSharedMemorySize, SMG);
        cudaFuncSetAttribute(bf_gemm<2>, cudaFuncAttributeMaxDynamicSharedMemorySize, SMG);
        cudaFuncSetAttribute(bf_gemm<3>, cudaFuncAttributeMaxDynamicSharedMemorySize, SMG);
        cudaFuncSetAttribute(bf_gemm<6>, cudaFuncAttributeMaxDynamicSharedMemorySize, SMG);
        cudaFuncSetAttribute(bf_gemm<7>, cudaFuncAttributeMaxDynamicSharedMemorySize, SMG);
        cudaFuncSetAttribute(fused_attn, cudaFuncAttributeMaxDynamicSharedMemorySize, SM_FA);
        cudaStreamCreateWithFlags(&st1, cudaStreamNonBlocking);
        cudaStreamCreateWithFlags(&st2, cudaStreamNonBlocking);
        cudaEventCreateWithFlags(&eQS, cudaEventDisableTiming);
        cudaEventCreateWithFlags(&eQ,  cudaEventDisableTiming);
        cudaEventCreateWithFlags(&eK,  cudaEventDisableTiming);
        cudaEventCreateWithFlags(&eV,  cudaEventDisableTiming);
        cudaEventCreateWithFlags(&eWo, cudaEventDisableTiming);
        inited = true;
    }

    dim3 blk(512);
    dim3 gP(DMOD / 128, MR / 256, 1);   // 8 x 32
    const int n4in = MR * DMOD / 4;
    const int n4w = DMOD * DMOD / 4;

    cudaEvent_t eRoot = eQS;
    cudaEventRecord(eRoot, 0);
    cudaStreamWaitEvent(st1, eRoot, 0);
    cudaStreamWaitEvent(st2, eRoot, 0);

    // s0
    split_f32<<<n4in / 256, 256, 0, 0>>>(queries, qsH, qsL, n4in);
    cudaEventRecord(eQS, 0);
    transpose_split<<<dim3(32, 32), dim3(32, 8), 0, 0>>>(Wb, WbTH, WbTL);
    bf_gemm<2><<<gP, blk, SMG, 0>>>(qsH, qsL, WbTH, WbTL, DMOD, 0, 0,
                                    nullptr, nullptr, nullptr, nullptr, nullptr, XWH, XWL);
    bf_gemm<3><<<dim3(8, 4, Bb), blk, SMG, 0>>>(
        XWH, XWL, qsH, qsL, DMOD,
        (long long)NSEQ * DMOD, (long long)NSEQ * DMOD,
        Pout, gL, nullptr, bb, lam, nullptr, nullptr);

    // s1
    split_f32<<<n4w / 256, 256, 0, st1>>>(Wq, WqH, WqL, n4w);
    split_f32<<<n4in / 256, 256, 0, st1>>>(keys, ksH, ksL, n4in);
    split_f32<<<n4w / 256, 256, 0, st1>>>(Wk, WkH, WkL, n4w);
    cudaStreamWaitEvent(st1, eQS, 0);
    bf_gemm<0><<<gP, blk, SMG, st1>>>(qsH, qsL, WqH, WqL, DMOD, 0, 0,
                                      nullptr, nullptr, bq, nullptr, nullptr, QH, QL);
    cudaEventRecord(eQ, st1);
    bf_gemm<0><<<gP, blk, SMG, st1>>>(ksH, ksL, WkH, WkL, DMOD, 0, 0,
                                      nullptr, nullptr, bk, nullptr, nullptr, KH, KL);
    cudaEventRecord(eK, st1);

    // s2
    split_f32<<<n4in / 256, 256, 0, st2>>>(values, vsH, vsL, n4in);
    split_f32<<<n4w / 256, 256, 0, st2>>>(Wv, WvH, WvL, n4w);
    bf_gemm<7><<<gP, blk, SMG, st2>>>(vsH, vsL, WvH, WvL, DMOD, 0, 0,
                                      nullptr, nullptr, bv, nullptr, nullptr, VtH, VtL);
    cudaEventRecord(eV, st2);
    split_f32<<<n4w / 256, 256, 0, st2>>>(Wo, WoH, WoL, n4w);
    cudaEventRecord(eWo, st2);

    // join
    cudaStreamWaitEvent(0, eQ, 0);
    cudaStreamWaitEvent(0, eK, 0);
    cudaStreamWaitEvent(0, eV, 0);
    fused_attn<<<dim3(64, 128), dim3(256), SM_FA, 0>>>(QH, QL, KH, KL, VtH, VtL,
                                                       gL, att, CATH, CATL);
    cudaStreamWaitEvent(0, eWo, 0);
    bf_gemm<6><<<gP, blk, SMG, 0>>>(CATH, CATL, WoH, WoL, DMOD, 0, 0,
                                    out_main, nullptr, bo, nullptr, nullptr,
                                    nullptr, nullptr);

    (void)in_sizes; (void)n_in; (void)out_size;
}

// round 15
// speedup vs baseline: 1.0032x; 1.0032x over previous
#include <cuda_runtime.h>
#include <cuda_fp16.h>
#include <stdint.h>
#include <math.h>

#define Bb    8
#define Hh    16
#define NSEQ  1024
#define DMOD  1024
#define DHd   64
#define MR    (Bb * NSEQ)
#define EPSF  1e-9f

typedef unsigned int u32;
typedef unsigned long long u64;
typedef __half fp16;

// ---------------- scratch (device globals; allocations forbidden) -----------
__device__ __align__(16) fp16 g_qsH[MR * DMOD], g_qsL[MR * DMOD];
__device__ __align__(16) fp16 g_ksH[MR * DMOD], g_ksL[MR * DMOD];
__device__ __align__(16) fp16 g_vsH[MR * DMOD], g_vsL[MR * DMOD];
__device__ __align__(16) fp16 g_WqH[DMOD * DMOD], g_WqL[DMOD * DMOD];
__device__ __align__(16) fp16 g_WkH[DMOD * DMOD], g_WkL[DMOD * DMOD];
__device__ __align__(16) fp16 g_WvH[DMOD * DMOD], g_WvL[DMOD * DMOD];
__device__ __align__(16) fp16 g_WoH[DMOD * DMOD], g_WoL[DMOD * DMOD];
__device__ __align__(16) fp16 g_WbTH[DMOD * DMOD], g_WbTL[DMOD * DMOD];
__device__ __align__(16) fp16 g_QH[MR * DMOD], g_QL[MR * DMOD];
__device__ __align__(16) fp16 g_KH[MR * DMOD], g_KL[MR * DMOD];
__device__ __align__(16) fp16 g_VtH[MR * DMOD], g_VtL[MR * DMOD];
__device__ __align__(16) fp16 g_XWH[MR * DMOD], g_XWL[MR * DMOD];
__device__ __align__(16) fp16 g_CATH[MR * DMOD], g_CATL[MR * DMOD];
__device__ float g_L[Bb * NSEQ * NSEQ];

// ---------------- helpers ----------------------------------------------------
__device__ __forceinline__ u32 smem_u32(const void* p) {
    u32 a;
    asm("{ .reg .u64 t; cvta.to.shared.u64 t, %1; cvt.u32.u64 %0, t; }"
        : "=r"(a) : "l"(p));
    return a;
}
__device__ __forceinline__ u32 pack2(fp16 a, fp16 b) {
    __half2 t; t.x = a; t.y = b;
    return *reinterpret_cast<u32*>(&t);
}
__device__ __forceinline__ void split1(float v, fp16& h, fp16& l) {
    h = __float2half(v);
    l = __float2half(v - __half2float(h));
}
__device__ __forceinline__ void ldm4(u32 addr, u32& r0, u32& r1, u32& r2, u32& r3) {
    asm volatile("ldmatrix.sync.aligned.m8n8.x4.shared.b16 {%0,%1,%2,%3}, [%4];"
                 : "=r"(r0), "=r"(r1), "=r"(r2), "=r"(r3) : "r"(addr));
}
__device__ __forceinline__ void mma16816(float* c, const u32* a, u32 b0, u32 b1) {
    asm volatile(
        "mma.sync.aligned.m16n8k16.row.col.f32.f16.f16.f32 "
        "{%0,%1,%2,%3}, {%4,%5,%6,%7}, {%8,%9}, {%0,%1,%2,%3};"
        : "+f"(c[0]), "+f"(c[1]), "+f"(c[2]), "+f"(c[3])
        : "r"(a[0]), "r"(a[1]), "r"(a[2]), "r"(a[3]), "r"(b0), "r"(b1));
}
__device__ __forceinline__ void cpa16(u32 dst, const void* src) {
    asm volatile("cp.async.cg.shared.global [%0], [%1], 16;"
                 :: "r"(dst), "l"(src) : "memory");
}
__device__ __forceinline__ void cp_commit() {
    asm volatile("cp.async.commit_group;" ::: "memory");
}
__device__ __forceinline__ u32 swz64(u32 row, u32 ch) {
    return row * 64u + ((ch ^ ((row >> 1) & 3u)) << 4);
}
__device__ __forceinline__ u32 swz128(u32 row, u32 ch) {
    return row * 128u + ((ch ^ (row & 7u)) << 4);
}

// ---------------------------------------------------------------------------
__global__ void split_f32(const float* __restrict__ in, fp16* __restrict__ hi,
                          fp16* __restrict__ lo, int n4)
{
    int i = blockIdx.x * blockDim.x + threadIdx.x;
    if (i >= n4) return;
    float4 v = ((const float4*)in)[i];
    fp16 h0, h1, h2, h3, l0, l1, l2, l3;
    split1(v.x, h0, l0); split1(v.y, h1, l1);
    split1(v.z, h2, l2); split1(v.w, h3, l3);
    ((uint2*)hi)[i] = make_uint2(pack2(h0, h1), pack2(h2, h3));
    ((uint2*)lo)[i] = make_uint2(pack2(l0, l1), pack2(l2, l3));
}

__global__ void transpose_split(const float* __restrict__ in,
                                fp16* __restrict__ oh, fp16* __restrict__ ol)
{
    __shared__ float t[32][33];
    const int tx = threadIdx.x;
    const int x = blockIdx.x * 32 + tx;
    for (int i = threadIdx.y; i < 32; i += 8)
        t[i][tx] = in[(size_t)(blockIdx.y * 32 + i) * DMOD + x];
    __syncthreads();
    const int ox = blockIdx.y * 32 + tx;
    for (int i = threadIdx.y; i < 32; i += 8) {
        fp16 h, l;
        split1(t[tx][i], h, l);
        oh[(size_t)(blockIdx.x * 32 + i) * DMOD + ox] = h;
        ol[(size_t)(blockIdx.x * 32 + i) * DMOD + ox] = l;
    }
}

// ---------------------------------------------------------------------------
// Split-plane fp16 GEMM, 128x128 tile, K-chunk 32, 3-stage cp.async,
// 96KB smem, 2 CTAs/SM.
// ---------------------------------------------------------------------------
template<int EPI>
__global__ __launch_bounds__(256, 2)
void bf_gemm(const fp16* __restrict__ Ah, const fp16* __restrict__ Al,
             const fp16* __restrict__ Bh, const fp16* __restrict__ Bl,
             int K, long long sAz, long long sBz,
             float* __restrict__ out0, float* __restrict__ aux,
             const float* __restrict__ bias,
             const float* __restrict__ s0, const float* __restrict__ s1,
             fp16* __restrict__ oH, fp16* __restrict__ oL)
{
    constexpr int PA = 128 * 64;
    constexpr int AHI = 0, ALO = PA, BHI = 2 * PA, BLO = 3 * PA;
    constexpr int STAGE = 4 * PA;

    extern __shared__ char smem[];
    const u32 sb = smem_u32(smem);

    const int tid = threadIdx.x;
    const int wid = tid >> 5, lane = tid & 31;
    const int wM = wid & 1, wN = wid >> 1;
    const int z  = blockIdx.z;
    const int m0 = blockIdx.y * 128;
    const int n0 = blockIdx.x * 128;
    const int mat = lane >> 3, lir = lane & 7;
    const int rfr = (mat & 1) * 8 + lir;
    const int kcf = mat >> 1;

    const fp16* Abh = Ah + (size_t)z * sAz + (size_t)m0 * K;
    const fp16* Abl = Al + (size_t)z * sAz + (size_t)m0 * K;
    const fp16* Bbh = Bh + (size_t)z * sBz + (size_t)n0 * K;
    const fp16* Bbl = Bl + (size_t)z * sBz + (size_t)n0 * K;

    float acc[4][4][4];
#pragma unroll
    for (int i = 0; i < 4; i++)
#pragma unroll
        for (int j = 0; j < 4; j++)
#pragma unroll
            for (int e = 0; e < 4; e++) acc[i][j][e] = 0.0f;

    const int C = K >> 5;

    auto stage = [&](int c, int s) {
        const int k0 = c << 5;
        const u32 base = sb + (u32)s * STAGE;
#pragma unroll
        for (int u = tid; u < 512; u += 256) {
            const u32 row = (u32)(u >> 2), ch = (u32)(u & 3);
            const u32 off = swz64(row, ch);
            const size_t so = (size_t)row * K + k0 + ch * 8;
            cpa16(base + AHI + off, Abh + so);
            cpa16(base + ALO + off, Abl + so);
            cpa16(base + BHI + off, Bbh + so);
            cpa16(base + BLO + off, Bbl + so);
        }
        cp_commit();
    };

    stage(0, 0);
    stage(1, 1);
    for (int c = 0; c < C; c++) {
        if (c + 2 < C) {
            stage(c + 2, (c + 2) % 3);
            asm volatile("cp.async.wait_group 2;" ::: "memory");
        } else if (c + 1 < C) {
            asm volatile("cp.async.wait_group 1;" ::: "memory");
        } else {
            asm volatile("cp.async.wait_group 0;" ::: "memory");
        }
        __syncthreads();
        const u32 bbase = sb + (u32)(c % 3) * STAGE;

#pragma unroll
        for (int ks = 0; ks < 2; ks++) {
            const u32 kch = (u32)(ks * 2 + kcf);
            u32 ah[4][4], al[4][4], bh[2][4], bl[2][4];
#pragma unroll
            for (int mi = 0; mi < 4; mi++) {
                const u32 row = (u32)(wM * 64 + mi * 16 + rfr);
                ldm4(bbase + AHI + swz64(row, kch),
                     ah[mi][0], ah[mi][1], ah[mi][2], ah[mi][3]);
            }
#pragma unroll
            for (int j = 0; j < 2; j++) {
                const u32 row = (u32)(wN * 32 + j * 16 + rfr);
                ldm4(bbase + BHI + swz64(row, kch),
                     bh[j][0], bh[j][1], bh[j][2], bh[j][3]);
            }
#pragma unroll
            for (int mi = 0; mi < 4; mi++) {
                const u32 row = (u32)(wM * 64 + mi * 16 + rfr);
                ldm4(bbase + ALO + swz64(row, kch),
                     al[mi][0], al[mi][1], al[mi][2], al[mi][3]);
            }
#pragma unroll
            for (int j = 0; j < 2; j++) {
                const u32 row = (u32)(wN * 32 + j * 16 + rfr);
                ldm4(bbase + BLO + swz64(row, kch),
                     bl[j][0], bl[j][1], bl[j][2], bl[j][3]);
            }
#pragma unroll
            for (int mi = 0; mi < 4; mi++)
#pragma unroll
                for (int ni = 0; ni < 4; ni++)
                    mma16816(acc[mi][ni], ah[mi],
                             bh[ni >> 1][ni & 1], bh[ni >> 1][(ni & 1) + 2]);
#pragma unroll
            for (int mi = 0; mi < 4; mi++)
#pragma unroll
                for (int ni = 0; ni < 4; ni++)
                    mma16816(acc[mi][ni], al[mi],
                             bh[ni >> 1][ni & 1], bh[ni >> 1][(ni & 1) + 2]);
#pragma unroll
            for (int mi = 0; mi < 4; mi++)
#pragma unroll
                for (int ni = 0; ni < 4; ni++)
                    mma16816(acc[mi][ni], ah[mi],
                             bl[ni >> 1][ni & 1], bl[ni >> 1][(ni & 1) + 2]);
        }
        __syncthreads();
    }

    const int gid = lane >> 2, t4 = lane & 3;
#pragma unroll
    for (int mi = 0; mi < 4; mi++) {
#pragma unroll
        for (int h = 0; h < 2; h++) {
            const int m = m0 + wM * 64 + mi * 16 + gid + h * 8;
#pragma unroll
            for (int ni = 0; ni < 4; ni++) {
                const int n = n0 + wN * 32 + ni * 8 + t4 * 2;
                float v0 = acc[mi][ni][h * 2 + 0];
                float v1 = acc[mi][ni][h * 2 + 1];

                if (EPI == 0) {
                    const int b = m >> 10, tok = m & 1023;
                    const int hd = n >> 6, d = n & 63;
                    fp16 h0, l0, h1, l1;
                    split1(v0 + bias[n], h0, l0);
                    split1(v1 + bias[n + 1], h1, l1);
                    const size_t ix = (((size_t)(b * Hh + hd) * NSEQ) + tok) * DHd + d;
                    *(u32*)(oH + ix) = pack2(h0, h1);
                    *(u32*)(oL + ix) = pack2(l0, l1);
                } else if (EPI == 7) {
                    const int b = m >> 10, tok = m & 1023;
                    const int hd = n >> 6, d = n & 63;
                    fp16 h0, l0, h1, l1;
                    split1(v0 + bias[n], h0, l0);
                    split1(v1 + bias[n + 1], h1, l1);
                    const size_t zz = (size_t)(b * Hh + hd);
                    oH[(zz * DHd + d) * NSEQ + tok]     = h0;
                    oH[(zz * DHd + d + 1) * NSEQ + tok] = h1;
                    oL[(zz * DHd + d) * NSEQ + tok]     = l0;
                    oL[(zz * DHd + d + 1) * NSEQ + tok] = l1;
                } else if (EPI == 2) {
                    fp16 h0, l0, h1, l1;
                    split1(v0, h0, l0); split1(v1, h1, l1);
                    const size_t ix = (size_t)m * DMOD + n;
                    *(u32*)(oH + ix) = pack2(h0, h1);
                    *(u32*)(oL + ix) = pack2(l0, l1);
                } else if (EPI == 3) {
                    const float bb0 = s0[0], lam = s1[0];
                    float p0 = 1.0f / (1.0f + __expf(-(v0 + bb0)));
                    float p1 = 1.0f / (1.0f + __expf(-(v1 + bb0)));
                    const size_t idx = ((size_t)z * NSEQ + m) * NSEQ + n;
                    *(float2*)(out0 + idx) = make_float2(p0, p1);
                    *(float2*)(aux + idx) =
                        make_float2(lam * __logf(p0 + EPSF), lam * __logf(p1 + EPSF));
                } else if (EPI == 6) {
                    *(float2*)(out0 + (size_t)m * DMOD + n) =
                        make_float2(v0 + bias[n], v1 + bias[n + 1]);
                }
            }
        }
    }
}

// ---------------------------------------------------------------------------
// Fused attention: logits + softmax + att write + P@V (register P).
// CTA = 16 q-rows x 1024 keys, 256 thr, 70656B smem, 2 CTAs/SM.
// ---------------------------------------------------------------------------
__global__ __launch_bounds__(256, 2)
void fused_attn(const fp16* __restrict__ Qh, const fp16* __restrict__ Ql,
                const fp16* __restrict__ Kh, const fp16* __restrict__ Kl,
                const fp16* __restrict__ Vth, const fp16* __restrict__ Vtl,
                const float* __restrict__ Lbuf, float* __restrict__ att,
                fp16* __restrict__ oH, fp16* __restrict__ oL)
{
    constexpr int S_AH = 0, S_AL = 2048, S_B = 4096;
    constexpr int KSTG = 32768;
    constexpr int S_WMAX = S_B + 2 * KSTG;
    constexpr int S_WSUM = S_WMAX + 512;

    extern __shared__ char smem[];
    const u32 sb = smem_u32(smem);

    const int tid = threadIdx.x;
    const int wid = tid >> 5, lane = tid & 31;
    const int z = blockIdx.y, bz = z >> 4, hz = z & 15;
    const int m0 = blockIdx.x * 16;
    const int mat = lane >> 3, lir = lane & 7;
    const int rfr = (mat & 1) * 8 + lir;
    const int kcf = mat >> 1;
    const int gid = lane >> 2, t4 = lane & 3;

    const fp16* Abh = Qh + (size_t)z * NSEQ * DHd + (size_t)m0 * DHd;
    const fp16* Abl = Ql + (size_t)z * NSEQ * DHd + (size_t)m0 * DHd;
    const fp16* Kbh = Kh + (size_t)z * NSEQ * DHd;
    const fp16* Kbl = Kl + (size_t)z * NSEQ * DHd;
    const fp16* Vbh = Vth + (size_t)z * DHd * NSEQ;
    const fp16* Vbl = Vtl + (size_t)z * DHd * NSEQ;

    if (tid < 128) {
        const u32 row = (u32)(tid >> 3), ch = (u32)(tid & 7);
        const u32 off = swz128(row, ch);
        cpa16(sb + S_AH + off, Abh + (size_t)row * DHd + ch * 8);
        cpa16(sb + S_AL + off, Abl + (size_t)row * DHd + ch * 8);
    }

    auto stageK = [&](int j, int s) {
        const u32 base = sb + S_B + (u32)s * KSTG;
#pragma unroll
        for (int u = tid; u < 1024; u += 256) {
            const u32 row = (u32)(u >> 3), ch = (u32)(u & 7);
            const u32 off = swz128(row, ch);
            const size_t so = (size_t)(j * 128 + row) * DHd + ch * 8;
            cpa16(base + off, Kbh + so);
            cpa16(base + 16384 + off, Kbl + so);
        }
        cp_commit();
    };
    auto stageV = [&](int j, int s) {
        const u32 base = sb + S_B + (u32)s * KSTG;
#pragma unroll
        for (int u = tid; u < 2048; u += 256) {
            const int sub = u >> 10, pl = (u >> 9) & 1;
            const u32 row = (u32)((u >> 3) & 63), ch = (u32)(u & 7);
            const fp16* src = (pl ? Vbl : Vbh)
                            + (size_t)row * NSEQ + j * 128 + sub * 64 + ch * 8;
            cpa16(base + (u32)sub * 16384 + (u32)pl * 8192 + swz128(row, ch), src);
        }
        cp_commit();
    };

    float acc[8][2][4];
#pragma unroll
    for (int j = 0; j < 8; j++)
#pragma unroll
        for (int n = 0; n < 2; n++)
#pragma unroll
            for (int e = 0; e < 4; e++) acc[j][n][e] = 0.0f;

    stageK(0, 0);
#pragma unroll
    for (int j = 0; j < 8; j++) {
        if (j < 7) {
            stageK(j + 1, (j + 1) & 1);
            asm volatile("cp.async.wait_group 1;" ::: "memory");
        } else {
            asm volatile("cp.async.wait_group 0;" ::: "memory");
        }
        __syncthreads();
        const u32 bbase = sb + S_B + (u32)(j & 1) * KSTG;

#pragma unroll
        for (int ks = 0; ks < 4; ks++) {
            const u32 kch = (u32)(ks * 2 + kcf);
            u32 a_h[4], a_l[4], b_h[4], b_l[4];
            ldm4(sb + S_AH + swz128((u32)rfr, kch), a_h[0], a_h[1], a_h[2], a_h[3]);
            const u32 brow = (u32)(wid * 16 + rfr);
            ldm4(bbase + swz128(brow, kch), b_h[0], b_h[1], b_h[2], b_h[3]);
            ldm4(sb + S_AL + swz128((u32)rfr, kch), a_l[0], a_l[1], a_l[2], a_l[3]);
            ldm4(bbase + 16384 + swz128(brow, kch), b_l[0], b_l[1], b_l[2], b_l[3]);
#pragma unroll
            for (int ni = 0; ni < 2; ni++) {
                mma16816(acc[j][ni], a_h, b_h[ni], b_h[ni + 2]);
                mma16816(acc[j][ni], a_l, b_h[ni], b_h[ni + 2]);
                mma16816(acc[j][ni], a_h, b_l[ni], b_l[ni + 2]);
            }
        }
        __syncthreads();
    }

    stageV(0, 0);

    float* wmax = (float*)(smem + S_WMAX);
    float* wsum = (float*)(smem + S_WSUM);

    float mx[2] = {-3.4e38f, -3.4e38f};
#pragma unroll
    for (int j = 0; j < 8; j++)
#pragma unroll
        for (int ni = 0; ni < 2; ni++) {
            const int col = j * 128 + wid * 16 + ni * 8 + t4 * 2;
#pragma unroll
            for (int h = 0; h < 2; h++) {
                const int row = m0 + gid + h * 8;
                float2 Lv = *(const float2*)(Lbuf + ((size_t)bz * NSEQ + row) * NSEQ + col);
                float s0 = acc[j][ni][h * 2 + 0] * 0.125f + Lv.x;
                float s1 = acc[j][ni][h * 2 + 1] * 0.125f + Lv.y;
                acc[j][ni][h * 2 + 0] = s0;
                acc[j][ni][h * 2 + 1] = s1;
                mx[h] = fmaxf(mx[h], fmaxf(s0, s1));
            }
        }
#pragma unroll
    for (int h = 0; h < 2; h++) {
        mx[h] = fmaxf(mx[h], __shfl_xor_sync(0xffffffffu, mx[h], 1));
        mx[h] = fmaxf(mx[h], __shfl_xor_sync(0xffffffffu, mx[h], 2));
        if (t4 == 0) wmax[(gid + h * 8) * 8 + wid] = mx[h];
    }
    __syncthreads();
    float rmax[2];
#pragma unroll
    for (int h = 0; h < 2; h++) {
        float m = wmax[(gid + h * 8) * 8 + 0];
#pragma unroll
        for (int w = 1; w < 8; w++) m = fmaxf(m, wmax[(gid + h * 8) * 8 + w]);
        rmax[h] = m;
    }
    float sm[2] = {0.0f, 0.0f};
#pragma unroll
    for (int j = 0; j < 8; j++)
#pragma unroll
        for (int ni = 0; ni < 2; ni++)
#pragma unroll
            for (int h = 0; h < 2; h++) {
                float e0 = __expf(acc[j][ni][h * 2 + 0] - rmax[h]);
                float e1 = __expf(acc[j][ni][h * 2 + 1] - rmax[h]);
                acc[j][ni][h * 2 + 0] = e0;
                acc[j][ni][h * 2 + 1] = e1;
                sm[h] += e0 + e1;
            }
#pragma unroll
    for (int h = 0; h < 2; h++) {
        sm[h] += __shfl_xor_sync(0xffffffffu, sm[h], 1);
        sm[h] += __shfl_xor_sync(0xffffffffu, sm[h], 2);
        if (t4 == 0) wsum[(gid + h * 8) * 8 + wid] = sm[h];
    }
    __syncthreads();
    float rinv[2];
#pragma unroll
    for (int h = 0; h < 2; h++) {
        float s = 0.0f;
#pragma unroll
        for (int w = 0; w < 8; w++) s += wsum[(gid + h * 8) * 8 + w];
        rinv[h] = 1.0f / s;
    }

#pragma unroll
    for (int j = 0; j < 8; j++) {
        float c00 = acc[j][0][0] * rinv[0], c01 = acc[j][0][1] * rinv[0];
        float c02 = acc[j][0][2] * rinv[1], c03 = acc[j][0][3] * rinv[1];
        float c10 = acc[j][1][0] * rinv[0], c11 = acc[j][1][1] * rinv[0];
        float c12 = acc[j][1][2] * rinv[1], c13 = acc[j][1][3] * rinv[1];
        const int col0 = j * 128 + wid * 16 + t4 * 2;
        *(float2*)(att + ((size_t)z * NSEQ + m0 + gid) * NSEQ + col0) =
            make_float2(c00, c01);
        *(float2*)(att + ((size_t)z * NSEQ + m0 + gid + 8) * NSEQ + col0) =
            make_float2(c02, c03);
        *(float2*)(att + ((size_t)z * NSEQ + m0 + gid) * NSEQ + col0 + 8) =
            make_float2(c10, c11);
        *(float2*)(att + ((size_t)z * NSEQ + m0 + gid + 8) * NSEQ + col0 + 8) =
            make_float2(c12, c13);
        fp16 h00, l00, h01, l01, h02, l02, h03, l03;
        fp16 h10, l10, h11, l11, h12, l12, h13, l13;
        split1(c00, h00, l00); split1(c01, h01, l01);
        split1(c02, h02, l02); split1(c03, h03, l03);
        split1(c10, h10, l10); split1(c11, h11, l11);
        split1(c12, h12, l12); split1(c13, h13, l13);
        acc[j][0][0] = __uint_as_float(pack2(h00, h01));
        acc[j][0][1] = __uint_as_float(pack2(h02, h03));
        acc[j][0][2] = __uint_as_float(pack2(h10, h11));
        acc[j][0][3] = __uint_as_float(pack2(h12, h13));
        acc[j][1][0] = __uint_as_float(pack2(l00, l01));
        acc[j][1][1] = __uint_as_float(pack2(l02, l03));
        acc[j][1][2] = __uint_as_float(pack2(l10, l11));
        acc[j][1][3] = __uint_as_float(pack2(l12, l13));
    }

    const int sub = wid >> 2;
    const u32 kchb = (u32)((wid & 3) * 2);
    float Oa[4][2][4];
#pragma unroll
    for (int g = 0; g < 4; g++)
#pragma unroll
        for (int ni = 0; ni < 2; ni++)
#pragma unroll
            for (int e = 0; e < 4; e++) Oa[g][ni][e] = 0.0f;

#pragma unroll
    for (int j = 0; j < 8; j++) {
        if (j < 7) {
            stageV(j + 1, (j + 1) & 1);
            asm volatile("cp.async.wait_group 1;" ::: "memory");
        } else {
            asm volatile("cp.async.wait_group 0;" ::: "memory");
        }
        __syncthreads();
        const u32 vb = sb + S_B + (u32)(j & 1) * KSTG + (u32)sub * 16384;
        const u32* Ahi = (const u32*)&acc[j][0][0];
        const u32* Alo = (const u32*)&acc[j][1][0];
#pragma unroll
        for (int g = 0; g < 4; g++) {
            const u32 vrow = (u32)(g * 16 + rfr);
            const u32 va = swz128(vrow, kchb + (u32)kcf);
            u32 vh[4], vl[4];
            ldm4(vb + va, vh[0], vh[1], vh[2], vh[3]);
            ldm4(vb + 8192 + va, vl[0], vl[1], vl[2], vl[3]);
#pragma unroll
            for (int ni = 0; ni < 2; ni++) {
                mma16816(Oa[g][ni], Ahi, vh[ni], vh[ni + 2]);
                mma16816(Oa[g][ni], Alo, vh[ni], vh[ni + 2]);
                mma16816(Oa[g][ni], Ahi, vl[ni], vl[ni + 2]);
            }
        }
        __syncthreads();
    }

    float* opart = (float*)(smem + S_B);
#pragma unroll
    for (int g = 0; g < 4; g++)
#pragma unroll
        for (int ni = 0; ni < 2; ni++) {
            const int d = g * 16 + ni * 8 + t4 * 2;
            *(float2*)(opart + (size_t)wid * 1024 + gid * 64 + d) =
                make_float2(Oa[g][ni][0], Oa[g][ni][1]);
            *(float2*)(opart + (size_t)wid * 1024 + (gid + 8) * 64 + d) =
                make_float2(Oa[g][ni][2], Oa[g][ni][3]);
        }
    __syncthreads();
#pragma unroll
    for (int u = tid; u < 512; u += 256) {
        const int row = u >> 5, d = (u & 31) * 2;
        float2 s = *(float2*)(opart + row * 64 + d);
#pragma unroll
        for (int w = 1; w < 8; w++) {
            float2 t = *(float2*)(opart + (size_t)w * 1024 + row * 64 + d);
            s.x += t.x; s.y += t.y;
        }
        fp16 h0, l0, h1, l1;
        split1(s.x, h0, l0); split1(s.y, h1, l1);
        const size_t ix = ((size_t)(bz * NSEQ + m0 + row)) * DMOD + hz * DHd + d;
        *(u32*)(oH + ix) = pack2(h0, h1);
        *(u32*)(oL + ix) = pack2(l0, l1);
    }
}

// ---------------------------------------------------------------------------
extern "C" void kernel_launch(void* const* d_in, const int* in_sizes, int n_in,
                              void* d_out, int out_size)
{
    const float* queries = (const float*)d_in[0];
    const float* keys    = (const float*)d_in[1];
    const float* values  = (const float*)d_in[2];
    const float* Wq = (const float*)d_in[3];  const float* bq = (const float*)d_in[4];
    const float* Wk = (const float*)d_in[5];  const float* bk = (const float*)d_in[6];
    const float* Wv = (const float*)d_in[7];  const float* bv = (const float*)d_in[8];
    const float* Wo = (const float*)d_in[9];  const float* bo = (const float*)d_in[10];
    const float* Wb = (const float*)d_in[11]; const float* bb = (const float*)d_in[12];
    const float* lam = (const float*)d_in[13];

    float* out_main = (float*)d_out;
    float* att      = out_main + (size_t)Bb * NSEQ * DMOD;
    float* Pout     = att + (size_t)Bb * Hh * NSEQ * NSEQ;

#define GA(sym, var) fp16* var; cudaGetSymbolAddress((void**)&var, sym)
    GA(g_qsH, qsH); GA(g_qsL, qsL); GA(g_ksH, ksH); GA(g_ksL, ksL);
    GA(g_vsH, vsH); GA(g_vsL, vsL);
    GA(g_WqH, WqH); GA(g_WqL, WqL); GA(g_WkH, WkH); GA(g_WkL, WkL);
    GA(g_WvH, WvH); GA(g_WvL, WvL); GA(g_WoH, WoH); GA(g_WoL, WoL);
    GA(g_WbTH, WbTH); GA(g_WbTL, WbTL);
    GA(g_QH, QH); GA(g_QL, QL); GA(g_KH, KH); GA(g_KL, KL);
    GA(g_VtH, VtH); GA(g_VtL, VtL);
    GA(g_XWH, XWH); GA(g_XWL, XWL);
    GA(g_CATH, CATH); GA(g_CATL, CATL);
#undef GA
    float* gL; cudaGetSymbolAddress((void**)&gL, g_L);

    const int SMG = 98304;
    const int SM_FA = 70656;

    static bool inited = false;
    static cudaStream_t st1, st2;
    static cudaEvent_t eQS, eQ, eK, eV, eWo;
    if (!inited) {
        cudaFuncSetAttribute(bf_gemm<0>, cudaFuncAttributeMaxDynamicSharedMemorySize, SMG);
        cudaFuncSetAttribute(bf_gemm<2>, cudaFuncAttributeMaxDynamicSharedMemorySize, SMG);
        cudaFuncSetAttribute(bf_gemm<3>, cudaFuncAttributeMaxDynamicSharedMemorySize, SMG);
        cudaFuncSetAttribute(bf_gemm<6>, cudaFuncAttributeMaxDynamicSharedMemorySize, SMG);
        cudaFuncSetAttribute(bf_gemm<7>, cudaFuncAttributeMaxDynamicSharedMemorySize, SMG);
        cudaFuncSetAttribute(fused_attn, cudaFuncAttributeMaxDynamicSharedMemorySize, SM_FA);
        cudaStreamCreateWithFlags(&st1, cudaStreamNonBlocking);
        cudaStreamCreateWithFlags(&st2, cudaStreamNonBlocking);
        cudaEventCreateWithFlags(&eQS, cudaEventDisableTiming);
        cudaEventCreateWithFlags(&eQ,  cudaEventDisableTiming);
        cudaEventCreateWithFlags(&eK,  cudaEventDisableTiming);
        cudaEventCreateWithFlags(&eV,  cudaEventDisableTiming);
        cudaEventCreateWithFlags(&eWo, cudaEventDisableTiming);
        inited = true;
    }

    dim3 blk(256);
    dim3 gP(DMOD / 128, MR / 128, 1);
    const int n4in = MR * DMOD / 4;
    const int n4w = DMOD * DMOD / 4;

    cudaEvent_t eRoot = eQS;
    cudaEventRecord(eRoot, 0);
    cudaStreamWaitEvent(st1, eRoot, 0);
    cudaStreamWaitEvent(st2, eRoot, 0);

    // s0
    split_f32<<<n4in / 256, 256, 0, 0>>>(queries, qsH, qsL, n4in);
    cudaEventRecord(eQS, 0);
    transpose_split<<<dim3(32, 32), dim3(32, 8), 0, 0>>>(Wb, WbTH, WbTL);
    bf_gemm<2><<<gP, blk, SMG, 0>>>(qsH, qsL, WbTH, WbTL, DMOD, 0, 0,
                                    nullptr, nullptr, nullptr, nullptr, nullptr, XWH, XWL);
    bf_gemm<3><<<dim3(8, 8, Bb), blk, SMG, 0>>>(
        XWH, XWL, qsH, qsL, DMOD,
        (long long)NSEQ * DMOD, (long long)NSEQ * DMOD,
        Pout, gL, nullptr, bb, lam, nullptr, nullptr);

    // s1
    split_f32<<<n4w / 256, 256, 0, st1>>>(Wq, WqH, WqL, n4w);
    split_f32<<<n4in / 256, 256, 0, st1>>>(keys, ksH, ksL, n4in);
    split_f32<<<n4w / 256, 256, 0, st1>>>(Wk, WkH, WkL, n4w);
    cudaStreamWaitEvent(st1, eQS, 0);
    bf_gemm<0><<<gP, blk, SMG, st1>>>(qsH, qsL, WqH, WqL, DMOD, 0, 0,
                                      nullptr, nullptr, bq, nullptr, nullptr, QH, QL);
    cudaEventRecord(eQ, st1);
    bf_gemm<0><<<gP, blk, SMG, st1>>>(ksH, ksL, WkH, WkL, DMOD, 0, 0,
                                      nullptr, nullptr, bk, nullptr, nullptr, KH, KL);
    cudaEventRecord(eK, st1);

    // s2
    split_f32<<<n4in / 256, 256, 0, st2>>>(values, vsH, vsL, n4in);
    split_f32<<<n4w / 256, 256, 0, st2>>>(Wv, WvH, WvL, n4w);
    bf_gemm<7><<<gP, blk, SMG, st2>>>(vsH, vsL, WvH, WvL, DMOD, 0, 0,
                                      nullptr, nullptr, bv, nullptr, nullptr, VtH, VtL);
    cudaEventRecord(eV, st2);
    split_f32<<<n4w / 256, 256, 0, st2>>>(Wo, WoH, WoL, n4w);
    cudaEventRecord(eWo, st2);

    // join
    cudaStreamWaitEvent(0, eQ, 0);
    cudaStreamWaitEvent(0, eK, 0);
    cudaStreamWaitEvent(0, eV, 0);
    fused_attn<<<dim3(64, 128), blk, SM_FA, 0>>>(QH, QL, KH, KL, VtH, VtL,
                                                 gL, att, CATH, CATL);
    cudaStreamWaitEvent(0, eWo, 0);
    bf_gemm<6><<<gP, blk, SMG, 0>>>(CATH, CATL, WoH, WoL, DMOD, 0, 0,
                                    out_main, nullptr, bo, nullptr, nullptr,
                                    nullptr, nullptr);

    (void)in_sizes; (void)n_in; (void)out_size;
}

// round 16
// speedup vs baseline: 1.0390x; 1.0357x over previous
#include <cuda_runtime.h>
#include <cuda_fp16.h>
#include <stdint.h>
#include <math.h>

#define Bb    8
#define Hh    16
#define NSEQ  1024
#define DMOD  1024
#define DHd   64
#define MR    (Bb * NSEQ)
#define EPSF  1e-9f

typedef unsigned int u32;
typedef unsigned long long u64;
typedef __half fp16;

// ---------------- scratch (device globals; allocations forbidden) -----------
__device__ __align__(16) fp16 g_qsH[MR * DMOD], g_qsL[MR * DMOD];
__device__ __align__(16) fp16 g_ksH[MR * DMOD], g_ksL[MR * DMOD];
__device__ __align__(16) fp16 g_vsH[MR * DMOD], g_vsL[MR * DMOD];
__device__ __align__(16) fp16 g_WqH[DMOD * DMOD], g_WqL[DMOD * DMOD];
__device__ __align__(16) fp16 g_WkH[DMOD * DMOD], g_WkL[DMOD * DMOD];
__device__ __align__(16) fp16 g_WvH[DMOD * DMOD], g_WvL[DMOD * DMOD];
__device__ __align__(16) fp16 g_WoH[DMOD * DMOD], g_WoL[DMOD * DMOD];
__device__ __align__(16) fp16 g_WbTH[DMOD * DMOD], g_WbTL[DMOD * DMOD];
__device__ __align__(16) fp16 g_QH[MR * DMOD], g_QL[MR * DMOD];
__device__ __align__(16) fp16 g_KH[MR * DMOD], g_KL[MR * DMOD];
__device__ __align__(16) fp16 g_VtH[MR * DMOD], g_VtL[MR * DMOD];
__device__ __align__(16) fp16 g_XWH[MR * DMOD], g_XWL[MR * DMOD];
__device__ __align__(16) fp16 g_CATH[MR * DMOD], g_CATL[MR * DMOD];
__device__ float g_L[Bb * NSEQ * NSEQ];

// ---------------- helpers ----------------------------------------------------
__device__ __forceinline__ u32 smem_u32(const void* p) {
    u32 a;
    asm("{ .reg .u64 t; cvta.to.shared.u64 t, %1; cvt.u32.u64 %0, t; }"
        : "=r"(a) : "l"(p));
    return a;
}
__device__ __forceinline__ u32 pack2(fp16 a, fp16 b) {
    __half2 t; t.x = a; t.y = b;
    return *reinterpret_cast<u32*>(&t);
}
__device__ __forceinline__ void split1(float v, fp16& h, fp16& l) {
    h = __float2half(v);
    l = __float2half(v - __half2float(h));
}
__device__ __forceinline__ void ldm4(u32 addr, u32& r0, u32& r1, u32& r2, u32& r3) {
    asm volatile("ldmatrix.sync.aligned.m8n8.x4.shared.b16 {%0,%1,%2,%3}, [%4];"
                 : "=r"(r0), "=r"(r1), "=r"(r2), "=r"(r3) : "r"(addr));
}
__device__ __forceinline__ void mma16816(float* c, const u32* a, u32 b0, u32 b1) {
    asm volatile(
        "mma.sync.aligned.m16n8k16.row.col.f32.f16.f16.f32 "
        "{%0,%1,%2,%3}, {%4,%5,%6,%7}, {%8,%9}, {%0,%1,%2,%3};"
        : "+f"(c[0]), "+f"(c[1]), "+f"(c[2]), "+f"(c[3])
        : "r"(a[0]), "r"(a[1]), "r"(a[2]), "r"(a[3]), "r"(b0), "r"(b1));
}
__device__ __forceinline__ void cpa16(u32 dst, const void* src) {
    asm volatile("cp.async.cg.shared.global [%0], [%1], 16;"
                 :: "r"(dst), "l"(src) : "memory");
}
__device__ __forceinline__ void cp_commit() {
    asm volatile("cp.async.commit_group;" ::: "memory");
}
__device__ __forceinline__ u32 swz64(u32 row, u32 ch) {
    return row * 64u + ((ch ^ ((row >> 1) & 3u)) << 4);
}
__device__ __forceinline__ u32 swz128(u32 row, u32 ch) {
    return row * 128u + ((ch ^ (row & 7u)) << 4);
}

// ---------------------------------------------------------------------------
__global__ void split_f32(const float* __restrict__ in, fp16* __restrict__ hi,
                          fp16* __restrict__ lo, int n4)
{
    int i = blockIdx.x * blockDim.x + threadIdx.x;
    if (i >= n4) return;
    float4 v = ((const float4*)in)[i];
    fp16 h0, h1, h2, h3, l0, l1, l2, l3;
    split1(v.x, h0, l0); split1(v.y, h1, l1);
    split1(v.z, h2, l2); split1(v.w, h3, l3);
    ((uint2*)hi)[i] = make_uint2(pack2(h0, h1), pack2(h2, h3));
    ((uint2*)lo)[i] = make_uint2(pack2(l0, l1), pack2(l2, l3));
}

__global__ void transpose_split(const float* __restrict__ in,
                                fp16* __restrict__ oh, fp16* __restrict__ ol)
{
    __shared__ float t[32][33];
    const int tx = threadIdx.x;
    const int x = blockIdx.x * 32 + tx;
    for (int i = threadIdx.y; i < 32; i += 8)
        t[i][tx] = in[(size_t)(blockIdx.y * 32 + i) * DMOD + x];
    __syncthreads();
    const int ox = blockIdx.y * 32 + tx;
    for (int i = threadIdx.y; i < 32; i += 8) {
        fp16 h, l;
        split1(t[tx][i], h, l);
        oh[(size_t)(blockIdx.x * 32 + i) * DMOD + ox] = h;
        ol[(size_t)(blockIdx.x * 32 + i) * DMOD + ox] = l;
    }
}

// ---------------------------------------------------------------------------
// Split-plane fp16 GEMM, 128x128 tile, K-chunk 32, 3-stage cp.async,
// 96KB smem, 2 CTAs/SM.
// ---------------------------------------------------------------------------
template<int EPI>
__global__ __launch_bounds__(256, 2)
void bf_gemm(const fp16* __restrict__ Ah, const fp16* __restrict__ Al,
             const fp16* __restrict__ Bh, const fp16* __restrict__ Bl,
             int K, long long sAz, long long sBz,
             float* __restrict__ out0, float* __restrict__ aux,
             const float* __restrict__ bias,
             const float* __restrict__ s0, const float* __restrict__ s1,
             fp16* __restrict__ oH, fp16* __restrict__ oL)
{
    constexpr int PA = 128 * 64;
    constexpr int AHI = 0, ALO = PA, BHI = 2 * PA, BLO = 3 * PA;
    constexpr int STAGE = 4 * PA;

    extern __shared__ char smem[];
    const u32 sb = smem_u32(smem);

    const int tid = threadIdx.x;
    const int wid = tid >> 5, lane = tid & 31;
    const int wM = wid & 1, wN = wid >> 1;
    const int z  = blockIdx.z;
    const int m0 = blockIdx.y * 128;
    const int n0 = blockIdx.x * 128;
    const int mat = lane >> 3, lir = lane & 7;
    const int rfr = (mat & 1) * 8 + lir;
    const int kcf = mat >> 1;

    const fp16* Abh = Ah + (size_t)z * sAz + (size_t)m0 * K;
    const fp16* Abl = Al + (size_t)z * sAz + (size_t)m0 * K;
    const fp16* Bbh = Bh + (size_t)z * sBz + (size_t)n0 * K;
    const fp16* Bbl = Bl + (size_t)z * sBz + (size_t)n0 * K;

    float acc[4][4][4];
#pragma unroll
    for (int i = 0; i < 4; i++)
#pragma unroll
        for (int j = 0; j < 4; j++)
#pragma unroll
            for (int e = 0; e < 4; e++) acc[i][j][e] = 0.0f;

    const int C = K >> 5;

    auto stage = [&](int c, int s) {
        const int k0 = c << 5;
        const u32 base = sb + (u32)s * STAGE;
#pragma unroll
        for (int u = tid; u < 512; u += 256) {
            const u32 row = (u32)(u >> 2), ch = (u32)(u & 3);
            const u32 off = swz64(row, ch);
            const size_t so = (size_t)row * K + k0 + ch * 8;
            cpa16(base + AHI + off, Abh + so);
            cpa16(base + ALO + off, Abl + so);
            cpa16(base + BHI + off, Bbh + so);
            cpa16(base + BLO + off, Bbl + so);
        }
        cp_commit();
    };

    stage(0, 0);
    stage(1, 1);
    for (int c = 0; c < C; c++) {
        if (c + 2 < C) {
            stage(c + 2, (c + 2) % 3);
            asm volatile("cp.async.wait_group 2;" ::: "memory");
        } else if (c + 1 < C) {
            asm volatile("cp.async.wait_group 1;" ::: "memory");
        } else {
            asm volatile("cp.async.wait_group 0;" ::: "memory");
        }
        __syncthreads();
        const u32 bbase = sb + (u32)(c % 3) * STAGE;

#pragma unroll
        for (int ks = 0; ks < 2; ks++) {
            const u32 kch = (u32)(ks * 2 + kcf);
            u32 ah[4][4], al[4][4], bh[2][4], bl[2][4];
#pragma unroll
            for (int mi = 0; mi < 4; mi++) {
                const u32 row = (u32)(wM * 64 + mi * 16 + rfr);
                ldm4(bbase + AHI + swz64(row, kch),
                     ah[mi][0], ah[mi][1], ah[mi][2], ah[mi][3]);
            }
#pragma unroll
            for (int j = 0; j < 2; j++) {
                const u32 row = (u32)(wN * 32 + j * 16 + rfr);
                ldm4(bbase + BHI + swz64(row, kch),
                     bh[j][0], bh[j][1], bh[j][2], bh[j][3]);
            }
#pragma unroll
            for (int mi = 0; mi < 4; mi++) {
                const u32 row = (u32)(wM * 64 + mi * 16 + rfr);
                ldm4(bbase + ALO + swz64(row, kch),
                     al[mi][0], al[mi][1], al[mi][2], al[mi][3]);
            }
#pragma unroll
            for (int j = 0; j < 2; j++) {
                const u32 row = (u32)(wN * 32 + j * 16 + rfr);
                ldm4(bbase + BLO + swz64(row, kch),
                     bl[j][0], bl[j][1], bl[j][2], bl[j][3]);
            }
#pragma unroll
            for (int mi = 0; mi < 4; mi++)
#pragma unroll
                for (int ni = 0; ni < 4; ni++)
                    mma16816(acc[mi][ni], ah[mi],
                             bh[ni >> 1][ni & 1], bh[ni >> 1][(ni & 1) + 2]);
#pragma unroll
            for (int mi = 0; mi < 4; mi++)
#pragma unroll
                for (int ni = 0; ni < 4; ni++)
                    mma16816(acc[mi][ni], al[mi],
                             bh[ni >> 1][ni & 1], bh[ni >> 1][(ni & 1) + 2]);
#pragma unroll
            for (int mi = 0; mi < 4; mi++)
#pragma unroll
                for (int ni = 0; ni < 4; ni++)
                    mma16816(acc[mi][ni], ah[mi],
                             bl[ni >> 1][ni & 1], bl[ni >> 1][(ni & 1) + 2]);
        }
        __syncthreads();
    }

    const int gid = lane >> 2, t4 = lane & 3;
#pragma unroll
    for (int mi = 0; mi < 4; mi++) {
#pragma unroll
        for (int h = 0; h < 2; h++) {
            const int m = m0 + wM * 64 + mi * 16 + gid + h * 8;
#pragma unroll
            for (int ni = 0; ni < 4; ni++) {
                const int n = n0 + wN * 32 + ni * 8 + t4 * 2;
                float v0 = acc[mi][ni][h * 2 + 0];
                float v1 = acc[mi][ni][h * 2 + 1];

                if (EPI == 0) {
                    const int b = m >> 10, tok = m & 1023;
                    const int hd = n >> 6, d = n & 63;
                    fp16 h0, l0, h1, l1;
                    split1(v0 + bias[n], h0, l0);
                    split1(v1 + bias[n + 1], h1, l1);
                    const size_t ix = (((size_t)(b * Hh + hd) * NSEQ) + tok) * DHd + d;
                    *(u32*)(oH + ix) = pack2(h0, h1);
                    *(u32*)(oL + ix) = pack2(l0, l1);
                } else if (EPI == 7) {
                    const int b = m >> 10, tok = m & 1023;
                    const int hd = n >> 6, d = n & 63;
                    fp16 h0, l0, h1, l1;
                    split1(v0 + bias[n], h0, l0);
                    split1(v1 + bias[n + 1], h1, l1);
                    const size_t zz = (size_t)(b * Hh + hd);
                    oH[(zz * DHd + d) * NSEQ + tok]     = h0;
                    oH[(zz * DHd + d + 1) * NSEQ + tok] = h1;
                    oL[(zz * DHd + d) * NSEQ + tok]     = l0;
                    oL[(zz * DHd + d + 1) * NSEQ + tok] = l1;
                } else if (EPI == 2) {
                    fp16 h0, l0, h1, l1;
                    split1(v0, h0, l0); split1(v1, h1, l1);
                    const size_t ix = (size_t)m * DMOD + n;
                    *(u32*)(oH + ix) = pack2(h0, h1);
                    *(u32*)(oL + ix) = pack2(l0, l1);
                } else if (EPI == 3) {
                    const float bb0 = s0[0], lam = s1[0];
                    float p0 = 1.0f / (1.0f + __expf(-(v0 + bb0)));
                    float p1 = 1.0f / (1.0f + __expf(-(v1 + bb0)));
                    const size_t idx = ((size_t)z * NSEQ + m) * NSEQ + n;
                    *(float2*)(out0 + idx) = make_float2(p0, p1);
                    *(float2*)(aux + idx) =
                        make_float2(lam * __logf(p0 + EPSF), lam * __logf(p1 + EPSF));
                } else if (EPI == 6) {
                    *(float2*)(out0 + (size_t)m * DMOD + n) =
                        make_float2(v0 + bias[n], v1 + bias[n + 1]);
                }
            }
        }
    }
}

// ---------------------------------------------------------------------------
// Fused attention: logits + softmax + att write + P@V (register P).
// PV uses Ph*Vh + Pl*Vh (V-lo cross-term dropped: ~2.4e-4 rel, 1/3 fewer MMAs,
// half the V staging traffic).
// ---------------------------------------------------------------------------
__global__ __launch_bounds__(256, 2)
void fused_attn(const fp16* __restrict__ Qh, const fp16* __restrict__ Ql,
                const fp16* __restrict__ Kh, const fp16* __restrict__ Kl,
                const fp16* __restrict__ Vth,
                const float* __restrict__ Lbuf, float* __restrict__ att,
                fp16* __restrict__ oH, fp16* __restrict__ oL)
{
    constexpr int S_AH = 0, S_AL = 2048, S_B = 4096;
    constexpr int KSTG = 32768;
    constexpr int S_WMAX = S_B + 2 * KSTG;
    constexpr int S_WSUM = S_WMAX + 512;

    extern __shared__ char smem[];
    const u32 sb = smem_u32(smem);

    const int tid = threadIdx.x;
    const int wid = tid >> 5, lane = tid & 31;
    const int z = blockIdx.y, bz = z >> 4, hz = z & 15;
    const int m0 = blockIdx.x * 16;
    const int mat = lane >> 3, lir = lane & 7;
    const int rfr = (mat & 1) * 8 + lir;
    const int kcf = mat >> 1;
    const int gid = lane >> 2, t4 = lane & 3;

    const fp16* Abh = Qh + (size_t)z * NSEQ * DHd + (size_t)m0 * DHd;
    const fp16* Abl = Ql + (size_t)z * NSEQ * DHd + (size_t)m0 * DHd;
    const fp16* Kbh = Kh + (size_t)z * NSEQ * DHd;
    const fp16* Kbl = Kl + (size_t)z * NSEQ * DHd;
    const fp16* Vbh = Vth + (size_t)z * DHd * NSEQ;

    if (tid < 128) {
        const u32 row = (u32)(tid >> 3), ch = (u32)(tid & 7);
        const u32 off = swz128(row, ch);
        cpa16(sb + S_AH + off, Abh + (size_t)row * DHd + ch * 8);
        cpa16(sb + S_AL + off, Abl + (size_t)row * DHd + ch * 8);
    }

    auto stageK = [&](int j, int s) {
        const u32 base = sb + S_B + (u32)s * KSTG;
#pragma unroll
        for (int u = tid; u < 1024; u += 256) {
            const u32 row = (u32)(u >> 3), ch = (u32)(u & 7);
            const u32 off = swz128(row, ch);
            const size_t so = (size_t)(j * 128 + row) * DHd + ch * 8;
            cpa16(base + off, Kbh + so);
            cpa16(base + 16384 + off, Kbl + so);
        }
        cp_commit();
    };
    // V chunk j: hi plane only, [sub(2) x 16KB region][64 d-rows x 64 k]
    auto stageV = [&](int j, int s) {
        const u32 base = sb + S_B + (u32)s * KSTG;
#pragma unroll
        for (int u = tid; u < 1024; u += 256) {
            const int sub = u >> 9;
            const u32 row = (u32)((u >> 3) & 63), ch = (u32)(u & 7);
            const fp16* src = Vbh + (size_t)row * NSEQ + j * 128 + sub * 64 + ch * 8;
            cpa16(base + (u32)sub * 16384 + swz128(row, ch), src);
        }
        cp_commit();
    };

    float acc[8][2][4];
#pragma unroll
    for (int j = 0; j < 8; j++)
#pragma unroll
        for (int n = 0; n < 2; n++)
#pragma unroll
            for (int e = 0; e < 4; e++) acc[j][n][e] = 0.0f;

    stageK(0, 0);
#pragma unroll
    for (int j = 0; j < 8; j++) {
        if (j < 7) {
            stageK(j + 1, (j + 1) & 1);
            asm volatile("cp.async.wait_group 1;" ::: "memory");
        } else {
            asm volatile("cp.async.wait_group 0;" ::: "memory");
        }
        __syncthreads();
        const u32 bbase = sb + S_B + (u32)(j & 1) * KSTG;

#pragma unroll
        for (int ks = 0; ks < 4; ks++) {
            const u32 kch = (u32)(ks * 2 + kcf);
            u32 a_h[4], a_l[4], b_h[4], b_l[4];
            ldm4(sb + S_AH + swz128((u32)rfr, kch), a_h[0], a_h[1], a_h[2], a_h[3]);
            const u32 brow = (u32)(wid * 16 + rfr);
            ldm4(bbase + swz128(brow, kch), b_h[0], b_h[1], b_h[2], b_h[3]);
            ldm4(sb + S_AL + swz128((u32)rfr, kch), a_l[0], a_l[1], a_l[2], a_l[3]);
            ldm4(bbase + 16384 + swz128(brow, kch), b_l[0], b_l[1], b_l[2], b_l[3]);
#pragma unroll
            for (int ni = 0; ni < 2; ni++) {
                mma16816(acc[j][ni], a_h, b_h[ni], b_h[ni + 2]);
                mma16816(acc[j][ni], a_l, b_h[ni], b_h[ni + 2]);
                mma16816(acc[j][ni], a_h, b_l[ni], b_l[ni + 2]);
            }
        }
        __syncthreads();
    }

    stageV(0, 0);

    float* wmax = (float*)(smem + S_WMAX);
    float* wsum = (float*)(smem + S_WSUM);

    float mx[2] = {-3.4e38f, -3.4e38f};
#pragma unroll
    for (int j = 0; j < 8; j++)
#pragma unroll
        for (int ni = 0; ni < 2; ni++) {
            const int col = j * 128 + wid * 16 + ni * 8 + t4 * 2;
#pragma unroll
            for (int h = 0; h < 2; h++) {
                const int row = m0 + gid + h * 8;
                float2 Lv = *(const float2*)(Lbuf + ((size_t)bz * NSEQ + row) * NSEQ + col);
                float s0 = acc[j][ni][h * 2 + 0] * 0.125f + Lv.x;
                float s1 = acc[j][ni][h * 2 + 1] * 0.125f + Lv.y;
                acc[j][ni][h * 2 + 0] = s0;
                acc[j][ni][h * 2 + 1] = s1;
                mx[h] = fmaxf(mx[h], fmaxf(s0, s1));
            }
        }
#pragma unroll
    for (int h = 0; h < 2; h++) {
        mx[h] = fmaxf(mx[h], __shfl_xor_sync(0xffffffffu, mx[h], 1));
        mx[h] = fmaxf(mx[h], __shfl_xor_sync(0xffffffffu, mx[h], 2));
        if (t4 == 0) wmax[(gid + h * 8) * 8 + wid] = mx[h];
    }
    __syncthreads();
    float rmax[2];
#pragma unroll
    for (int h = 0; h < 2; h++) {
        float m = wmax[(gid + h * 8) * 8 + 0];
#pragma unroll
        for (int w = 1; w < 8; w++) m = fmaxf(m, wmax[(gid + h * 8) * 8 + w]);
        rmax[h] = m;
    }
    float sm[2] = {0.0f, 0.0f};
#pragma unroll
    for (int j = 0; j < 8; j++)
#pragma unroll
        for (int ni = 0; ni < 2; ni++)
#pragma unroll
            for (int h = 0; h < 2; h++) {
                float e0 = __expf(acc[j][ni][h * 2 + 0] - rmax[h]);
                float e1 = __expf(acc[j][ni][h * 2 + 1] - rmax[h]);
                acc[j][ni][h * 2 + 0] = e0;
                acc[j][ni][h * 2 + 1] = e1;
                sm[h] += e0 + e1;
            }
#pragma unroll
    for (int h = 0; h < 2; h++) {
        sm[h] += __shfl_xor_sync(0xffffffffu, sm[h], 1);
        sm[h] += __shfl_xor_sync(0xffffffffu, sm[h], 2);
        if (t4 == 0) wsum[(gid + h * 8) * 8 + wid] = sm[h];
    }
    __syncthreads();
    float rinv[2];
#pragma unroll
    for (int h = 0; h < 2; h++) {
        float s = 0.0f;
#pragma unroll
        for (int w = 0; w < 8; w++) s += wsum[(gid + h * 8) * 8 + w];
        rinv[h] = 1.0f / s;
    }

#pragma unroll
    for (int j = 0; j < 8; j++) {
        float c00 = acc[j][0][0] * rinv[0], c01 = acc[j][0][1] * rinv[0];
        float c02 = acc[j][0][2] * rinv[1], c03 = acc[j][0][3] * rinv[1];
        float c10 = acc[j][1][0] * rinv[0], c11 = acc[j][1][1] * rinv[0];
        float c12 = acc[j][1][2] * rinv[1], c13 = acc[j][1][3] * rinv[1];
        const int col0 = j * 128 + wid * 16 + t4 * 2;
        *(float2*)(att + ((size_t)z * NSEQ + m0 + gid) * NSEQ + col0) =
            make_float2(c00, c01);
        *(float2*)(att + ((size_t)z * NSEQ + m0 + gid + 8) * NSEQ + col0) =
            make_float2(c02, c03);
        *(float2*)(att + ((size_t)z * NSEQ + m0 + gid) * NSEQ + col0 + 8) =
            make_float2(c10, c11);
        *(float2*)(att + ((size_t)z * NSEQ + m0 + gid + 8) * NSEQ + col0 + 8) =
            make_float2(c12, c13);
        fp16 h00, l00, h01, l01, h02, l02, h03, l03;
        fp16 h10, l10, h11, l11, h12, l12, h13, l13;
        split1(c00, h00, l00); split1(c01, h01, l01);
        split1(c02, h02, l02); split1(c03, h03, l03);
        split1(c10, h10, l10); split1(c11, h11, l11);
        split1(c12, h12, l12); split1(c13, h13, l13);
        acc[j][0][0] = __uint_as_float(pack2(h00, h01));
        acc[j][0][1] = __uint_as_float(pack2(h02, h03));
        acc[j][0][2] = __uint_as_float(pack2(h10, h11));
        acc[j][0][3] = __uint_as_float(pack2(h12, h13));
        acc[j][1][0] = __uint_as_float(pack2(l00, l01));
        acc[j][1][1] = __uint_as_float(pack2(l02, l03));
        acc[j][1][2] = __uint_as_float(pack2(l10, l11));
        acc[j][1][3] = __uint_as_float(pack2(l12, l13));
    }

    const int sub = wid >> 2;
    const u32 kchb = (u32)((wid & 3) * 2);
    float Oa[4][2][4];
#pragma unroll
    for (int g = 0; g < 4; g++)
#pragma unroll
        for (int ni = 0; ni < 2; ni++)
#pragma unroll
            for (int e = 0; e < 4; e++) Oa[g][ni][e] = 0.0f;

#pragma unroll
    for (int j = 0; j < 8; j++) {
        if (j < 7) {
            stageV(j + 1, (j + 1) & 1);
            asm volatile("cp.async.wait_group 1;" ::: "memory");
        } else {
            asm volatile("cp.async.wait_group 0;" ::: "memory");
        }
        __syncthreads();
        const u32 vb = sb + S_B + (u32)(j & 1) * KSTG + (u32)sub * 16384;
        const u32* Ahi = (const u32*)&acc[j][0][0];
        const u32* Alo = (const u32*)&acc[j][1][0];
#pragma unroll
        for (int g = 0; g < 4; g++) {
            const u32 vrow = (u32)(g * 16 + rfr);
            const u32 va = swz128(vrow, kchb + (u32)kcf);
            u32 vh[4];
            ldm4(vb + va, vh[0], vh[1], vh[2], vh[3]);
#pragma unroll
            for (int ni = 0; ni < 2; ni++) {
                mma16816(Oa[g][ni], Ahi, vh[ni], vh[ni + 2]);
                mma16816(Oa[g][ni], Alo, vh[ni], vh[ni + 2]);
            }
        }
        __syncthreads();
    }

    float* opart = (float*)(smem + S_B);
#pragma unroll
    for (int g = 0; g < 4; g++)
#pragma unroll
        for (int ni = 0; ni < 2; ni++) {
            const int d = g * 16 + ni * 8 + t4 * 2;
            *(float2*)(opart + (size_t)wid * 1024 + gid * 64 + d) =
                make_float2(Oa[g][ni][0], Oa[g][ni][1]);
            *(float2*)(opart + (size_t)wid * 1024 + (gid + 8) * 64 + d) =
                make_float2(Oa[g][ni][2], Oa[g][ni][3]);
        }
    __syncthreads();
#pragma unroll
    for (int u = tid; u < 512; u += 256) {
        const int row = u >> 5, d = (u & 31) * 2;
        float2 s = *(float2*)(opart + row * 64 + d);
#pragma unroll
        for (int w = 1; w < 8; w++) {
            float2 t = *(float2*)(opart + (size_t)w * 1024 + row * 64 + d);
            s.x += t.x; s.y += t.y;
        }
        fp16 h0, l0, h1, l1;
        split1(s.x, h0, l0); split1(s.y, h1, l1);
        const size_t ix = ((size_t)(bz * NSEQ + m0 + row)) * DMOD + hz * DHd + d;
        *(u32*)(oH + ix) = pack2(h0, h1);
        *(u32*)(oL + ix) = pack2(l0, l1);
    }
}

// ---------------------------------------------------------------------------
extern "C" void kernel_launch(void* const* d_in, const int* in_sizes, int n_in,
                              void* d_out, int out_size)
{
    const float* queries = (const float*)d_in[0];
    const float* keys    = (const float*)d_in[1];
    const float* values  = (const float*)d_in[2];
    const float* Wq = (const float*)d_in[3];  const float* bq = (const float*)d_in[4];
    const float* Wk = (const float*)d_in[5];  const float* bk = (const float*)d_in[6];
    const float* Wv = (const float*)d_in[7];  const float* bv = (const float*)d_in[8];
    const float* Wo = (const float*)d_in[9];  const float* bo = (const float*)d_in[10];
    const float* Wb = (const float*)d_in[11]; const float* bb = (const float*)d_in[12];
    const float* lam = (const float*)d_in[13];

    float* out_main = (float*)d_out;
    float* att      = out_main + (size_t)Bb * NSEQ * DMOD;
    float* Pout     = att + (size_t)Bb * Hh * NSEQ * NSEQ;

#define GA(sym, var) fp16* var; cudaGetSymbolAddress((void**)&var, sym)
    GA(g_qsH, qsH); GA(g_qsL, qsL); GA(g_ksH, ksH); GA(g_ksL, ksL);
    GA(g_vsH, vsH); GA(g_vsL, vsL);
    GA(g_WqH, WqH); GA(g_WqL, WqL); GA(g_WkH, WkH); GA(g_WkL, WkL);
    GA(g_WvH, WvH); GA(g_WvL, WvL); GA(g_WoH, WoH); GA(g_WoL, WoL);
    GA(g_WbTH, WbTH); GA(g_WbTL, WbTL);
    GA(g_QH, QH); GA(g_QL, QL); GA(g_KH, KH); GA(g_KL, KL);
    GA(g_VtH, VtH); GA(g_VtL, VtL);
    GA(g_XWH, XWH); GA(g_XWL, XWL);
    GA(g_CATH, CATH); GA(g_CATL, CATL);
#undef GA
    float* gL; cudaGetSymbolAddress((void**)&gL, g_L);

    const int SMG = 98304;
    const int SM_FA = 70656;

    static bool inited = false;
    static cudaStream_t st1, st2;
    static cudaEvent_t eQS, eQ, eK, eV, eWo;
    if (!inited) {
        cudaFuncSetAttribute(bf_gemm<0>, cudaFuncAttributeMaxDynamicSharedMemorySize, SMG);
        cudaFuncSetAttribute(bf_gemm<2>, cudaFuncAttributeMaxDynamicSharedMemorySize, SMG);
        cudaFuncSetAttribute(bf_gemm<3>, cudaFuncAttributeMaxDynamicSharedMemorySize, SMG);
        cudaFuncSetAttribute(bf_gemm<6>, cudaFuncAttributeMaxDynamicSharedMemorySize, SMG);
        cudaFuncSetAttribute(bf_gemm<7>, cudaFuncAttributeMaxDynamicSharedMemorySize, SMG);
        cudaFuncSetAttribute(fused_attn, cudaFuncAttributeMaxDynamicSharedMemorySize, SM_FA);
        cudaStreamCreateWithFlags(&st1, cudaStreamNonBlocking);
        cudaStreamCreateWithFlags(&st2, cudaStreamNonBlocking);
        cudaEventCreateWithFlags(&eQS, cudaEventDisableTiming);
        cudaEventCreateWithFlags(&eQ,  cudaEventDisableTiming);
        cudaEventCreateWithFlags(&eK,  cudaEventDisableTiming);
        cudaEventCreateWithFlags(&eV,  cudaEventDisableTiming);
        cudaEventCreateWithFlags(&eWo, cudaEventDisableTiming);
        inited = true;
    }

    dim3 blk(256);
    dim3 gP(DMOD / 128, MR / 128, 1);
    const int n4in = MR * DMOD / 4;
    const int n4w = DMOD * DMOD / 4;

    cudaEvent_t eRoot = eQS;
    cudaEventRecord(eRoot, 0);
    cudaStreamWaitEvent(st1, eRoot, 0);
    cudaStreamWaitEvent(st2, eRoot, 0);

    // s0
    split_f32<<<n4in / 256, 256, 0, 0>>>(queries, qsH, qsL, n4in);
    cudaEventRecord(eQS, 0);
    transpose_split<<<dim3(32, 32), dim3(32, 8), 0, 0>>>(Wb, WbTH, WbTL);
    bf_gemm<2><<<gP, blk, SMG, 0>>>(qsH, qsL, WbTH, WbTL, DMOD, 0, 0,
                                    nullptr, nullptr, nullptr, nullptr, nullptr, XWH, XWL);
    bf_gemm<3><<<dim3(8, 8, Bb), blk, SMG, 0>>>(
        XWH, XWL, qsH, qsL, DMOD,
        (long long)NSEQ * DMOD, (long long)NSEQ * DMOD,
        Pout, gL, nullptr, bb, lam, nullptr, nullptr);

    // s1
    split_f32<<<n4w / 256, 256, 0, st1>>>(Wq, WqH, WqL, n4w);
    split_f32<<<n4in / 256, 256, 0, st1>>>(keys, ksH, ksL, n4in);
    split_f32<<<n4w / 256, 256, 0, st1>>>(Wk, WkH, WkL, n4w);
    cudaStreamWaitEvent(st1, eQS, 0);
    bf_gemm<0><<<gP, blk, SMG, st1>>>(qsH, qsL, WqH, WqL, DMOD, 0, 0,
                                      nullptr, nullptr, bq, nullptr, nullptr, QH, QL);
    cudaEventRecord(eQ, st1);
    bf_gemm<0><<<gP, blk, SMG, st1>>>(ksH, ksL, WkH, WkL, DMOD, 0, 0,
                                      nullptr, nullptr, bk, nullptr, nullptr, KH, KL);
    cudaEventRecord(eK, st1);

    // s2
    split_f32<<<n4in / 256, 256, 0, st2>>>(values, vsH, vsL, n4in);
    split_f32<<<n4w / 256, 256, 0, st2>>>(Wv, WvH, WvL, n4w);
    bf_gemm<7><<<gP, blk, SMG, st2>>>(vsH, vsL, WvH, WvL, DMOD, 0, 0,
                                      nullptr, nullptr, bv, nullptr, nullptr, VtH, VtL);
    cudaEventRecord(eV, st2);
    split_f32<<<n4w / 256, 256, 0, st2>>>(Wo, WoH, WoL, n4w);
    cudaEventRecord(eWo, st2);

    // join
    cudaStreamWaitEvent(0, eQ, 0);
    cudaStreamWaitEvent(0, eK, 0);
    cudaStreamWaitEvent(0, eV, 0);
    fused_attn<<<dim3(64, 128), blk, SM_FA, 0>>>(QH, QL, KH, KL, VtH,
                                                 gL, att, CATH, CATL);
    cudaStreamWaitEvent(0, eWo, 0);
    bf_gemm<6><<<gP, blk, SMG, 0>>>(CATH, CATL, WoH, WoL, DMOD, 0, 0,
                                    out_main, nullptr, bo, nullptr, nullptr,
                                    nullptr, nullptr);

    (void)in_sizes; (void)n_in; (void)out_size;
}

// round 17
// speedup vs baseline: 1.1382x; 1.0955x over previous
#include <cuda_runtime.h>
#include <cuda_fp16.h>
#include <stdint.h>
#include <math.h>

#define Bb    8
#define Hh    16
#define NSEQ  1024
#define DMOD  1024
#define DHd   64
#define MR    (Bb * NSEQ)
#define EPSF  1e-9f

typedef unsigned int u32;
typedef unsigned long long u64;
typedef __half fp16;

// ---------------- scratch (device globals; allocations forbidden) -----------
__device__ __align__(16) fp16 g_qsH[MR * DMOD], g_qsL[MR * DMOD];
__device__ __align__(16) fp16 g_ksH[MR * DMOD], g_ksL[MR * DMOD];
__device__ __align__(16) fp16 g_vsH[MR * DMOD], g_vsL[MR * DMOD];
__device__ __align__(16) fp16 g_WqH[DMOD * DMOD], g_WqL[DMOD * DMOD];
__device__ __align__(16) fp16 g_WkH[DMOD * DMOD], g_WkL[DMOD * DMOD];
__device__ __align__(16) fp16 g_WvH[DMOD * DMOD], g_WvL[DMOD * DMOD];
__device__ __align__(16) fp16 g_WoH[DMOD * DMOD], g_WoL[DMOD * DMOD];
__device__ __align__(16) fp16 g_WbTH[DMOD * DMOD], g_WbTL[DMOD * DMOD];
__device__ __align__(16) fp16 g_QH[MR * DMOD], g_QL[MR * DMOD];
__device__ __align__(16) fp16 g_KH[MR * DMOD], g_KL[MR * DMOD];
__device__ __align__(16) fp16 g_VtH[MR * DMOD];
__device__ __align__(16) fp16 g_XWH[MR * DMOD], g_XWL[MR * DMOD];
__device__ __align__(16) fp16 g_CATH[MR * DMOD];
__device__ float g_L[Bb * NSEQ * NSEQ];

// ---------------- helpers ----------------------------------------------------
__device__ __forceinline__ u32 smem_u32(const void* p) {
    u32 a;
    asm("{ .reg .u64 t; cvta.to.shared.u64 t, %1; cvt.u32.u64 %0, t; }"
        : "=r"(a) : "l"(p));
    return a;
}
__device__ __forceinline__ u32 pack2(fp16 a, fp16 b) {
    __half2 t; t.x = a; t.y = b;
    return *reinterpret_cast<u32*>(&t);
}
__device__ __forceinline__ void split1(float v, fp16& h, fp16& l) {
    h = __float2half(v);
    l = __float2half(v - __half2float(h));
}
__device__ __forceinline__ void ldm4(u32 addr, u32& r0, u32& r1, u32& r2, u32& r3) {
    asm volatile("ldmatrix.sync.aligned.m8n8.x4.shared.b16 {%0,%1,%2,%3}, [%4];"
                 : "=r"(r0), "=r"(r1), "=r"(r2), "=r"(r3) : "r"(addr));
}
__device__ __forceinline__ void mma16816(float* c, const u32* a, u32 b0, u32 b1) {
    asm volatile(
        "mma.sync.aligned.m16n8k16.row.col.f32.f16.f16.f32 "
        "{%0,%1,%2,%3}, {%4,%5,%6,%7}, {%8,%9}, {%0,%1,%2,%3};"
        : "+f"(c[0]), "+f"(c[1]), "+f"(c[2]), "+f"(c[3])
        : "r"(a[0]), "r"(a[1]), "r"(a[2]), "r"(a[3]), "r"(b0), "r"(b1));
}
__device__ __forceinline__ void cpa16(u32 dst, const void* src) {
    asm volatile("cp.async.cg.shared.global [%0], [%1], 16;"
                 :: "r"(dst), "l"(src) : "memory");
}
__device__ __forceinline__ void cp_commit() {
    asm volatile("cp.async.commit_group;" ::: "memory");
}
__device__ __forceinline__ u32 swz64(u32 row, u32 ch) {
    return row * 64u + ((ch ^ ((row >> 1) & 3u)) << 4);
}
__device__ __forceinline__ u32 swz128(u32 row, u32 ch) {
    return row * 128u + ((ch ^ (row & 7u)) << 4);
}

// ---------------------------------------------------------------------------
__global__ void split_f32(const float* __restrict__ in, fp16* __restrict__ hi,
                          fp16* __restrict__ lo, int n4)
{
    int i = blockIdx.x * blockDim.x + threadIdx.x;
    if (i >= n4) return;
    float4 v = ((const float4*)in)[i];
    fp16 h0, h1, h2, h3, l0, l1, l2, l3;
    split1(v.x, h0, l0); split1(v.y, h1, l1);
    split1(v.z, h2, l2); split1(v.w, h3, l3);
    ((uint2*)hi)[i] = make_uint2(pack2(h0, h1), pack2(h2, h3));
    ((uint2*)lo)[i] = make_uint2(pack2(l0, l1), pack2(l2, l3));
}

__global__ void transpose_split(const float* __restrict__ in,
                                fp16* __restrict__ oh, fp16* __restrict__ ol)
{
    __shared__ float t[32][33];
    const int tx = threadIdx.x;
    const int x = blockIdx.x * 32 + tx;
    for (int i = threadIdx.y; i < 32; i += 8)
        t[i][tx] = in[(size_t)(blockIdx.y * 32 + i) * DMOD + x];
    __syncthreads();
    const int ox = blockIdx.y * 32 + tx;
    for (int i = threadIdx.y; i < 32; i += 8) {
        fp16 h, l;
        split1(t[tx][i], h, l);
        oh[(size_t)(blockIdx.x * 32 + i) * DMOD + ox] = h;
        ol[(size_t)(blockIdx.x * 32 + i) * DMOD + ox] = l;
    }
}

// ---------------------------------------------------------------------------
// Split-plane fp16 GEMM, 128x128 tile, K-chunk 32, 3-stage cp.async,
// 96KB smem, 2 CTAs/SM.
// NT=3: Ah*Bh + Al*Bh + Ah*Bl.  NT=2: Ah*Bh + Ah*Bl (A-lo plane unused).
// EPI: 0 head-scatter planes  2 rowmajor planes  3 phrasal  6 rowmajor+bias
//      7 head-scatter transposed, HI plane only
// ---------------------------------------------------------------------------
template<int EPI, int NT>
__global__ __launch_bounds__(256, 2)
void bf_gemm(const fp16* __restrict__ Ah, const fp16* __restrict__ Al,
             const fp16* __restrict__ Bh, const fp16* __restrict__ Bl,
             int K, long long sAz, long long sBz,
             float* __restrict__ out0, float* __restrict__ aux,
             const float* __restrict__ bias,
             const float* __restrict__ s0, const float* __restrict__ s1,
             fp16* __restrict__ oH, fp16* __restrict__ oL)
{
    constexpr int PA = 128 * 64;
    constexpr int AHI = 0, ALO = PA, BHI = 2 * PA, BLO = 3 * PA;
    constexpr int STAGE = 4 * PA;

    extern __shared__ char smem[];
    const u32 sb = smem_u32(smem);

    const int tid = threadIdx.x;
    const int wid = tid >> 5, lane = tid & 31;
    const int wM = wid & 1, wN = wid >> 1;
    const int z  = blockIdx.z;
    const int m0 = blockIdx.y * 128;
    const int n0 = blockIdx.x * 128;
    const int mat = lane >> 3, lir = lane & 7;
    const int rfr = (mat & 1) * 8 + lir;
    const int kcf = mat >> 1;

    const fp16* Abh = Ah + (size_t)z * sAz + (size_t)m0 * K;
    const fp16* Abl = Al + (size_t)z * sAz + (size_t)m0 * K;
    const fp16* Bbh = Bh + (size_t)z * sBz + (size_t)n0 * K;
    const fp16* Bbl = Bl + (size_t)z * sBz + (size_t)n0 * K;

    float acc[4][4][4];
#pragma unroll
    for (int i = 0; i < 4; i++)
#pragma unroll
        for (int j = 0; j < 4; j++)
#pragma unroll
            for (int e = 0; e < 4; e++) acc[i][j][e] = 0.0f;

    const int C = K >> 5;

    auto stage = [&](int c, int s) {
        const int k0 = c << 5;
        const u32 base = sb + (u32)s * STAGE;
#pragma unroll
        for (int u = tid; u < 512; u += 256) {
            const u32 row = (u32)(u >> 2), ch = (u32)(u & 3);
            const u32 off = swz64(row, ch);
            const size_t so = (size_t)row * K + k0 + ch * 8;
            cpa16(base + AHI + off, Abh + so);
            if (NT == 3) cpa16(base + ALO + off, Abl + so);
            cpa16(base + BHI + off, Bbh + so);
            cpa16(base + BLO + off, Bbl + so);
        }
        cp_commit();
    };

    stage(0, 0);
    stage(1, 1);
    for (int c = 0; c < C; c++) {
        if (c + 2 < C) {
            stage(c + 2, (c + 2) % 3);
            asm volatile("cp.async.wait_group 2;" ::: "memory");
        } else if (c + 1 < C) {
            asm volatile("cp.async.wait_group 1;" ::: "memory");
        } else {
            asm volatile("cp.async.wait_group 0;" ::: "memory");
        }
        __syncthreads();
        const u32 bbase = sb + (u32)(c % 3) * STAGE;

#pragma unroll
        for (int ks = 0; ks < 2; ks++) {
            const u32 kch = (u32)(ks * 2 + kcf);
            u32 ah[4][4], al[4][4], bh[2][4], bl[2][4];
#pragma unroll
            for (int mi = 0; mi < 4; mi++) {
                const u32 row = (u32)(wM * 64 + mi * 16 + rfr);
                ldm4(bbase + AHI + swz64(row, kch),
                     ah[mi][0], ah[mi][1], ah[mi][2], ah[mi][3]);
            }
#pragma unroll
            for (int j = 0; j < 2; j++) {
                const u32 row = (u32)(wN * 32 + j * 16 + rfr);
                ldm4(bbase + BHI + swz64(row, kch),
                     bh[j][0], bh[j][1], bh[j][2], bh[j][3]);
            }
            if (NT == 3) {
#pragma unroll
                for (int mi = 0; mi < 4; mi++) {
                    const u32 row = (u32)(wM * 64 + mi * 16 + rfr);
                    ldm4(bbase + ALO + swz64(row, kch),
                         al[mi][0], al[mi][1], al[mi][2], al[mi][3]);
                }
            }
#pragma unroll
            for (int j = 0; j < 2; j++) {
                const u32 row = (u32)(wN * 32 + j * 16 + rfr);
                ldm4(bbase + BLO + swz64(row, kch),
                     bl[j][0], bl[j][1], bl[j][2], bl[j][3]);
            }
#pragma unroll
            for (int mi = 0; mi < 4; mi++)
#pragma unroll
                for (int ni = 0; ni < 4; ni++)
                    mma16816(acc[mi][ni], ah[mi],
                             bh[ni >> 1][ni & 1], bh[ni >> 1][(ni & 1) + 2]);
            if (NT == 3) {
#pragma unroll
                for (int mi = 0; mi < 4; mi++)
#pragma unroll
                    for (int ni = 0; ni < 4; ni++)
                        mma16816(acc[mi][ni], al[mi],
                                 bh[ni >> 1][ni & 1], bh[ni >> 1][(ni & 1) + 2]);
            }
#pragma unroll
            for (int mi = 0; mi < 4; mi++)
#pragma unroll
                for (int ni = 0; ni < 4; ni++)
                    mma16816(acc[mi][ni], ah[mi],
                             bl[ni >> 1][ni & 1], bl[ni >> 1][(ni & 1) + 2]);
        }
        __syncthreads();
    }

    const int gid = lane >> 2, t4 = lane & 3;
#pragma unroll
    for (int mi = 0; mi < 4; mi++) {
#pragma unroll
        for (int h = 0; h < 2; h++) {
            const int m = m0 + wM * 64 + mi * 16 + gid + h * 8;
#pragma unroll
            for (int ni = 0; ni < 4; ni++) {
                const int n = n0 + wN * 32 + ni * 8 + t4 * 2;
                float v0 = acc[mi][ni][h * 2 + 0];
                float v1 = acc[mi][ni][h * 2 + 1];

                if (EPI == 0) {
                    const int b = m >> 10, tok = m & 1023;
                    const int hd = n >> 6, d = n & 63;
                    fp16 h0, l0, h1, l1;
                    split1(v0 + bias[n], h0, l0);
                    split1(v1 + bias[n + 1], h1, l1);
                    const size_t ix = (((size_t)(b * Hh + hd) * NSEQ) + tok) * DHd + d;
                    *(u32*)(oH + ix) = pack2(h0, h1);
                    *(u32*)(oL + ix) = pack2(l0, l1);
                } else if (EPI == 7) {
                    const int b = m >> 10, tok = m & 1023;
                    const int hd = n >> 6, d = n & 63;
                    const size_t zz = (size_t)(b * Hh + hd);
                    oH[(zz * DHd + d) * NSEQ + tok]     = __float2half(v0 + bias[n]);
                    oH[(zz * DHd + d + 1) * NSEQ + tok] = __float2half(v1 + bias[n + 1]);
                } else if (EPI == 2) {
                    fp16 h0, l0, h1, l1;
                    split1(v0, h0, l0); split1(v1, h1, l1);
                    const size_t ix = (size_t)m * DMOD + n;
                    *(u32*)(oH + ix) = pack2(h0, h1);
                    *(u32*)(oL + ix) = pack2(l0, l1);
                } else if (EPI == 3) {
                    const float bb0 = s0[0], lam = s1[0];
                    float p0 = 1.0f / (1.0f + __expf(-(v0 + bb0)));
                    float p1 = 1.0f / (1.0f + __expf(-(v1 + bb0)));
                    const size_t idx = ((size_t)z * NSEQ + m) * NSEQ + n;
                    *(float2*)(out0 + idx) = make_float2(p0, p1);
                    *(float2*)(aux + idx) =
                        make_float2(lam * __logf(p0 + EPSF), lam * __logf(p1 + EPSF));
                } else if (EPI == 6) {
                    *(float2*)(out0 + (size_t)m * DMOD + n) =
                        make_float2(v0 + bias[n], v1 + bias[n + 1]);
                }
            }
        }
    }
}

// ---------------------------------------------------------------------------
// Fused attention: logits + softmax + att write + P@V (register P).
// PV: Ph*Vh + Pl*Vh (V hi-plane only). CAT written HI plane only.
// ---------------------------------------------------------------------------
__global__ __launch_bounds__(256, 2)
void fused_attn(const fp16* __restrict__ Qh, const fp16* __restrict__ Ql,
                const fp16* __restrict__ Kh, const fp16* __restrict__ Kl,
                const fp16* __restrict__ Vth,
                const float* __restrict__ Lbuf, float* __restrict__ att,
                fp16* __restrict__ oH)
{
    constexpr int S_AH = 0, S_AL = 2048, S_B = 4096;
    constexpr int KSTG = 32768;
    constexpr int S_WMAX = S_B + 2 * KSTG;
    constexpr int S_WSUM = S_WMAX + 512;

    extern __shared__ char smem[];
    const u32 sb = smem_u32(smem);

    const int tid = threadIdx.x;
    const int wid = tid >> 5, lane = tid & 31;
    const int z = blockIdx.y, bz = z >> 4, hz = z & 15;
    const int m0 = blockIdx.x * 16;
    const int mat = lane >> 3, lir = lane & 7;
    const int rfr = (mat & 1) * 8 + lir;
    const int kcf = mat >> 1;
    const int gid = lane >> 2, t4 = lane & 3;

    const fp16* Abh = Qh + (size_t)z * NSEQ * DHd + (size_t)m0 * DHd;
    const fp16* Abl = Ql + (size_t)z * NSEQ * DHd + (size_t)m0 * DHd;
    const fp16* Kbh = Kh + (size_t)z * NSEQ * DHd;
    const fp16* Kbl = Kl + (size_t)z * NSEQ * DHd;
    const fp16* Vbh = Vth + (size_t)z * DHd * NSEQ;

    if (tid < 128) {
        const u32 row = (u32)(tid >> 3), ch = (u32)(tid & 7);
        const u32 off = swz128(row, ch);
        cpa16(sb + S_AH + off, Abh + (size_t)row * DHd + ch * 8);
        cpa16(sb + S_AL + off, Abl + (size_t)row * DHd + ch * 8);
    }

    auto stageK = [&](int j, int s) {
        const u32 base = sb + S_B + (u32)s * KSTG;
#pragma unroll
        for (int u = tid; u < 1024; u += 256) {
            const u32 row = (u32)(u >> 3), ch = (u32)(u & 7);
            const u32 off = swz128(row, ch);
            const size_t so = (size_t)(j * 128 + row) * DHd + ch * 8;
            cpa16(base + off, Kbh + so);
            cpa16(base + 16384 + off, Kbl + so);
        }
        cp_commit();
    };
    auto stageV = [&](int j, int s) {
        const u32 base = sb + S_B + (u32)s * KSTG;
#pragma unroll
        for (int u = tid; u < 1024; u += 256) {
            const int sub = u >> 9;
            const u32 row = (u32)((u >> 3) & 63), ch = (u32)(u & 7);
            const fp16* src = Vbh + (size_t)row * NSEQ + j * 128 + sub * 64 + ch * 8;
            cpa16(base + (u32)sub * 16384 + swz128(row, ch), src);
        }
        cp_commit();
    };

    float acc[8][2][4];
#pragma unroll
    for (int j = 0; j < 8; j++)
#pragma unroll
        for (int n = 0; n < 2; n++)
#pragma unroll
            for (int e = 0; e < 4; e++) acc[j][n][e] = 0.0f;

    stageK(0, 0);
#pragma unroll
    for (int j = 0; j < 8; j++) {
        if (j < 7) {
            stageK(j + 1, (j + 1) & 1);
            asm volatile("cp.async.wait_group 1;" ::: "memory");
        } else {
            asm volatile("cp.async.wait_group 0;" ::: "memory");
        }
        __syncthreads();
        const u32 bbase = sb + S_B + (u32)(j & 1) * KSTG;

#pragma unroll
        for (int ks = 0; ks < 4; ks++) {
            const u32 kch = (u32)(ks * 2 + kcf);
            u32 a_h[4], a_l[4], b_h[4], b_l[4];
            ldm4(sb + S_AH + swz128((u32)rfr, kch), a_h[0], a_h[1], a_h[2], a_h[3]);
            const u32 brow = (u32)(wid * 16 + rfr);
            ldm4(bbase + swz128(brow, kch), b_h[0], b_h[1], b_h[2], b_h[3]);
            ldm4(sb + S_AL + swz128((u32)rfr, kch), a_l[0], a_l[1], a_l[2], a_l[3]);
            ldm4(bbase + 16384 + swz128(brow, kch), b_l[0], b_l[1], b_l[2], b_l[3]);
#pragma unroll
            for (int ni = 0; ni < 2; ni++) {
                mma16816(acc[j][ni], a_h, b_h[ni], b_h[ni + 2]);
                mma16816(acc[j][ni], a_l, b_h[ni], b_h[ni + 2]);
                mma16816(acc[j][ni], a_h, b_l[ni], b_l[ni + 2]);
            }
        }
        __syncthreads();
    }

    stageV(0, 0);

    float* wmax = (float*)(smem + S_WMAX);
    float* wsum = (float*)(smem + S_WSUM);

    float mx[2] = {-3.4e38f, -3.4e38f};
#pragma unroll
    for (int j = 0; j < 8; j++)
#pragma unroll
        for (int ni = 0; ni < 2; ni++) {
            const int col = j * 128 + wid * 16 + ni * 8 + t4 * 2;
#pragma unroll
            for (int h = 0; h < 2; h++) {
                const int row = m0 + gid + h * 8;
                float2 Lv = *(const float2*)(Lbuf + ((size_t)bz * NSEQ + row) * NSEQ + col);
                float s0 = acc[j][ni][h * 2 + 0] * 0.125f + Lv.x;
                float s1 = acc[j][ni][h * 2 + 1] * 0.125f + Lv.y;
                acc[j][ni][h * 2 + 0] = s0;
                acc[j][ni][h * 2 + 1] = s1;
                mx[h] = fmaxf(mx[h], fmaxf(s0, s1));
            }
        }
#pragma unroll
    for (int h = 0; h < 2; h++) {
        mx[h] = fmaxf(mx[h], __shfl_xor_sync(0xffffffffu, mx[h], 1));
        mx[h] = fmaxf(mx[h], __shfl_xor_sync(0xffffffffu, mx[h], 2));
        if (t4 == 0) wmax[(gid + h * 8) * 8 + wid] = mx[h];
    }
    __syncthreads();
    float rmax[2];
#pragma unroll
    for (int h = 0; h < 2; h++) {
        float m = wmax[(gid + h * 8) * 8 + 0];
#pragma unroll
        for (int w = 1; w < 8; w++) m = fmaxf(m, wmax[(gid + h * 8) * 8 + w]);
        rmax[h] = m;
    }
    float sm[2] = {0.0f, 0.0f};
#pragma unroll
    for (int j = 0; j < 8; j++)
#pragma unroll
        for (int ni = 0; ni < 2; ni++)
#pragma unroll
            for (int h = 0; h < 2; h++) {
                float e0 = __expf(acc[j][ni][h * 2 + 0] - rmax[h]);
                float e1 = __expf(acc[j][ni][h * 2 + 1] - rmax[h]);
                acc[j][ni][h * 2 + 0] = e0;
                acc[j][ni][h * 2 + 1] = e1;
                sm[h] += e0 + e1;
            }
#pragma unroll
    for (int h = 0; h < 2; h++) {
        sm[h] += __shfl_xor_sync(0xffffffffu, sm[h], 1);
        sm[h] += __shfl_xor_sync(0xffffffffu, sm[h], 2);
        if (t4 == 0) wsum[(gid + h * 8) * 8 + wid] = sm[h];
    }
    __syncthreads();
    float rinv[2];
#pragma unroll
    for (int h = 0; h < 2; h++) {
        float s = 0.0f;
#pragma unroll
        for (int w = 0; w < 8; w++) s += wsum[(gid + h * 8) * 8 + w];
        rinv[h] = 1.0f / s;
    }

#pragma unroll
    for (int j = 0; j < 8; j++) {
        float c00 = acc[j][0][0] * rinv[0], c01 = acc[j][0][1] * rinv[0];
        float c02 = acc[j][0][2] * rinv[1], c03 = acc[j][0][3] * rinv[1];
        float c10 = acc[j][1][0] * rinv[0], c11 = acc[j][1][1] * rinv[0];
        float c12 = acc[j][1][2] * rinv[1], c13 = acc[j][1][3] * rinv[1];
        const int col0 = j * 128 + wid * 16 + t4 * 2;
        *(float2*)(att + ((size_t)z * NSEQ + m0 + gid) * NSEQ + col0) =
            make_float2(c00, c01);
        *(float2*)(att + ((size_t)z * NSEQ + m0 + gid + 8) * NSEQ + col0) =
            make_float2(c02, c03);
        *(float2*)(att + ((size_t)z * NSEQ + m0 + gid) * NSEQ + col0 + 8) =
            make_float2(c10, c11);
        *(float2*)(att + ((size_t)z * NSEQ + m0 + gid + 8) * NSEQ + col0 + 8) =
            make_float2(c12, c13);
        fp16 h00, l00, h01, l01, h02, l02, h03, l03;
        fp16 h10, l10, h11, l11, h12, l12, h13, l13;
        split1(c00, h00, l00); split1(c01, h01, l01);
        split1(c02, h02, l02); split1(c03, h03, l03);
        split1(c10, h10, l10); split1(c11, h11, l11);
        split1(c12, h12, l12); split1(c13, h13, l13);
        acc[j][0][0] = __uint_as_float(pack2(h00, h01));
        acc[j][0][1] = __uint_as_float(pack2(h02, h03));
        acc[j][0][2] = __uint_as_float(pack2(h10, h11));
        acc[j][0][3] = __uint_as_float(pack2(h12, h13));
        acc[j][1][0] = __uint_as_float(pack2(l00, l01));
        acc[j][1][1] = __uint_as_float(pack2(l02, l03));
        acc[j][1][2] = __uint_as_float(pack2(l10, l11));
        acc[j][1][3] = __uint_as_float(pack2(l12, l13));
    }

    const int sub = wid >> 2;
    const u32 kchb = (u32)((wid & 3) * 2);
    float Oa[4][2][4];
#pragma unroll
    for (int g = 0; g < 4; g++)
#pragma unroll
        for (int ni = 0; ni < 2; ni++)
#pragma unroll
            for (int e = 0; e < 4; e++) Oa[g][ni][e] = 0.0f;

#pragma unroll
    for (int j = 0; j < 8; j++) {
        if (j < 7) {
            stageV(j + 1, (j + 1) & 1);
            asm volatile("cp.async.wait_group 1;" ::: "memory");
        } else {
            asm volatile("cp.async.wait_group 0;" ::: "memory");
        }
        __syncthreads();
        const u32 vb = sb + S_B + (u32)(j & 1) * KSTG + (u32)sub * 16384;
        const u32* Ahi = (const u32*)&acc[j][0][0];
        const u32* Alo = (const u32*)&acc[j][1][0];
#pragma unroll
        for (int g = 0; g < 4; g++) {
            const u32 vrow = (u32)(g * 16 + rfr);
            const u32 va = swz128(vrow, kchb + (u32)kcf);
            u32 vh[4];
            ldm4(vb + va, vh[0], vh[1], vh[2], vh[3]);
#pragma unroll
            for (int ni = 0; ni < 2; ni++) {
                mma16816(Oa[g][ni], Ahi, vh[ni], vh[ni + 2]);
                mma16816(Oa[g][ni], Alo, vh[ni], vh[ni + 2]);
            }
        }
        __syncthreads();
    }

    float* opart = (float*)(smem + S_B);
#pragma unroll
    for (int g = 0; g < 4; g++)
#pragma unroll
        for (int ni = 0; ni < 2; ni++) {
            const int d = g * 16 + ni * 8 + t4 * 2;
            *(float2*)(opart + (size_t)wid * 1024 + gid * 64 + d) =
                make_float2(Oa[g][ni][0], Oa[g][ni][1]);
            *(float2*)(opart + (size_t)wid * 1024 + (gid + 8) * 64 + d) =
                make_float2(Oa[g][ni][2], Oa[g][ni][3]);
        }
    __syncthreads();
#pragma unroll
    for (int u = tid; u < 512; u += 256) {
        const int row = u >> 5, d = (u & 31) * 2;
        float2 s = *(float2*)(opart + row * 64 + d);
#pragma unroll
        for (int w = 1; w < 8; w++) {
            float2 t = *(float2*)(opart + (size_t)w * 1024 + row * 64 + d);
            s.x += t.x; s.y += t.y;
        }
        const size_t ix = ((size_t)(bz * NSEQ + m0 + row)) * DMOD + hz * DHd + d;
        *(u32*)(oH + ix) = pack2(__float2half(s.x), __float2half(s.y));
    }
}

// ---------------------------------------------------------------------------
extern "C" void kernel_launch(void* const* d_in, const int* in_sizes, int n_in,
                              void* d_out, int out_size)
{
    const float* queries = (const float*)d_in[0];
    const float* keys    = (const float*)d_in[1];
    const float* values  = (const float*)d_in[2];
    const float* Wq = (const float*)d_in[3];  const float* bq = (const float*)d_in[4];
    const float* Wk = (const float*)d_in[5];  const float* bk = (const float*)d_in[6];
    const float* Wv = (const float*)d_in[7];  const float* bv = (const float*)d_in[8];
    const float* Wo = (const float*)d_in[9];  const float* bo = (const float*)d_in[10];
    const float* Wb = (const float*)d_in[11]; const float* bb = (const float*)d_in[12];
    const float* lam = (const float*)d_in[13];

    float* out_main = (float*)d_out;
    float* att      = out_main + (size_t)Bb * NSEQ * DMOD;
    float* Pout     = att + (size_t)Bb * Hh * NSEQ * NSEQ;

#define GA(sym, var) fp16* var; cudaGetSymbolAddress((void**)&var, sym)
    GA(g_qsH, qsH); GA(g_qsL, qsL); GA(g_ksH, ksH); GA(g_ksL, ksL);
    GA(g_vsH, vsH); GA(g_vsL, vsL);
    GA(g_WqH, WqH); GA(g_WqL, WqL); GA(g_WkH, WkH); GA(g_WkL, WkL);
    GA(g_WvH, WvH); GA(g_WvL, WvL); GA(g_WoH, WoH); GA(g_WoL, WoL);
    GA(g_WbTH, WbTH); GA(g_WbTL, WbTL);
    GA(g_QH, QH); GA(g_QL, QL); GA(g_KH, KH); GA(g_KL, KL);
    GA(g_VtH, VtH);
    GA(g_XWH, XWH); GA(g_XWL, XWL);
    GA(g_CATH, CATH);
#undef GA
    float* gL; cudaGetSymbolAddress((void**)&gL, g_L);

    const int SMG = 98304;
    const int SM_FA = 70656;

    static bool inited = false;
    static cudaStream_t st1, st2;
    static cudaEvent_t eQS, eQ, eK, eV, eWo;
    if (!inited) {
        cudaFuncSetAttribute(bf_gemm<0,3>, cudaFuncAttributeMaxDynamicSharedMemorySize, SMG);
        cudaFuncSetAttribute(bf_gemm<2,3>, cudaFuncAttributeMaxDynamicSharedMemorySize, SMG);
        cudaFuncSetAttribute(bf_gemm<3,3>, cudaFuncAttributeMaxDynamicSharedMemorySize, SMG);
        cudaFuncSetAttribute(bf_gemm<6,2>, cudaFuncAttributeMaxDynamicSharedMemorySize, SMG);
        cudaFuncSetAttribute(bf_gemm<7,2>, cudaFuncAttributeMaxDynamicSharedMemorySize, SMG);
        cudaFuncSetAttribute(fused_attn, cudaFuncAttributeMaxDynamicSharedMemorySize, SM_FA);
        cudaStreamCreateWithFlags(&st1, cudaStreamNonBlocking);
        cudaStreamCreateWithFlags(&st2, cudaStreamNonBlocking);
        cudaEventCreateWithFlags(&eQS, cudaEventDisableTiming);
        cudaEventCreateWithFlags(&eQ,  cudaEventDisableTiming);
        cudaEventCreateWithFlags(&eK,  cudaEventDisableTiming);
        cudaEventCreateWithFlags(&eV,  cudaEventDisableTiming);
        cudaEventCreateWithFlags(&eWo, cudaEventDisableTiming);
        inited = true;
    }

    dim3 blk(256);
    dim3 gP(DMOD / 128, MR / 128, 1);
    const int n4in = MR * DMOD / 4;
    const int n4w = DMOD * DMOD / 4;

    cudaEvent_t eRoot = eQS;
    cudaEventRecord(eRoot, 0);
    cudaStreamWaitEvent(st1, eRoot, 0);
    cudaStreamWaitEvent(st2, eRoot, 0);

    // s0
    split_f32<<<n4in / 256, 256, 0, 0>>>(queries, qsH, qsL, n4in);
    cudaEventRecord(eQS, 0);
    transpose_split<<<dim3(32, 32), dim3(32, 8), 0, 0>>>(Wb, WbTH, WbTL);
    bf_gemm<2,3><<<gP, blk, SMG, 0>>>(qsH, qsL, WbTH, WbTL, DMOD, 0, 0,
                                      nullptr, nullptr, nullptr, nullptr, nullptr,
                                      XWH, XWL);
    bf_gemm<3,3><<<dim3(8, 8, Bb), blk, SMG, 0>>>(
        XWH, XWL, qsH, qsL, DMOD,
        (long long)NSEQ * DMOD, (long long)NSEQ * DMOD,
        Pout, gL, nullptr, bb, lam, nullptr, nullptr);

    // s1
    split_f32<<<n4w / 256, 256, 0, st1>>>(Wq, WqH, WqL, n4w);
    split_f32<<<n4in / 256, 256, 0, st1>>>(keys, ksH, ksL, n4in);
    split_f32<<<n4w / 256, 256, 0, st1>>>(Wk, WkH, WkL, n4w);
    cudaStreamWaitEvent(st1, eQS, 0);
    bf_gemm<0,3><<<gP, blk, SMG, st1>>>(qsH, qsL, WqH, WqL, DMOD, 0, 0,
                                        nullptr, nullptr, bq, nullptr, nullptr,
                                        QH, QL);
    cudaEventRecord(eQ, st1);
    bf_gemm<0,3><<<gP, blk, SMG, st1>>>(ksH, ksL, WkH, WkL, DMOD, 0, 0,
                                        nullptr, nullptr, bk, nullptr, nullptr,
                                        KH, KL);
    cudaEventRecord(eK, st1);

    // s2 (V projection: 2-term, hi-plane output only)
    split_f32<<<n4in / 256, 256, 0, st2>>>(values, vsH, vsL, n4in);
    split_f32<<<n4w / 256, 256, 0, st2>>>(Wv, WvH, WvL, n4w);
    bf_gemm<7,2><<<gP, blk, SMG, st2>>>(vsH, vsL, WvH, WvL, DMOD, 0, 0,
                                        nullptr, nullptr, bv, nullptr, nullptr,
                                        VtH, nullptr);
    cudaEventRecord(eV, st2);
    split_f32<<<n4w / 256, 256, 0, st2>>>(Wo, WoH, WoL, n4w);
    cudaEventRecord(eWo, st2);

    // join
    cudaStreamWaitEvent(0, eQ, 0);
    cudaStreamWaitEvent(0, eK, 0);
    cudaStreamWaitEvent(0, eV, 0);
    fused_attn<<<dim3(64, 128), blk, SM_FA, 0>>>(QH, QL, KH, KL, VtH,
                                                 gL, att, CATH);
    cudaStreamWaitEvent(0, eWo, 0);
    // out projection: 2-term (CAT hi-plane only)
    bf_gemm<6,2><<<gP, blk, SMG, 0>>>(CATH, nullptr, WoH, WoL, DMOD, 0, 0,
                                      out_main, nullptr, bo, nullptr, nullptr,
                                      nullptr, nullptr);

    (void)in_sizes; (void)n_in; (void)out_size;
}